// round 7
// baseline (speedup 1.0000x reference)
#include <cuda_runtime.h>
#include <math.h>
#include <stdint.h>

// Problem constants
#define BATCH   4
#define TSEQ    2048
#define NHEAD   16
#define HSIZE   64
#define CEMB    1024
#define MROWS   (BATCH*TSEQ)   // 8192

// Scratch (device globals: allocation-free rule)
__device__ float g_q[(size_t)BATCH * NHEAD * TSEQ * HSIZE];   // [B,H,T,D], q pre-scaled
__device__ float g_k[(size_t)BATCH * NHEAD * TSEQ * HSIZE];   // [B,H,T,D]
__device__ float g_v[(size_t)BATCH * NHEAD * TSEQ * HSIZE];   // [B,H,D,T]  (transposed!)
__device__ float g_attn[(size_t)MROWS * CEMB];                // [B*T, C]
__device__ float g_wt_qkv[(size_t)3 * CEMB * CEMB];           // [3C, C] K-major
__device__ float g_wt_proj[(size_t)CEMB * CEMB];              // [C, C]  K-major

// ---------------------------------------------------------------------------
// tf32 helpers
// ---------------------------------------------------------------------------
__device__ __forceinline__ uint32_t f2tf32(float x) {
    uint32_t r;
    asm("cvt.rna.tf32.f32 %0, %1;" : "=r"(r) : "f"(x));
    return r;
}
__device__ __forceinline__ float4 cvt4(float4 v) {
    v.x = __uint_as_float(f2tf32(v.x)); v.y = __uint_as_float(f2tf32(v.y));
    v.z = __uint_as_float(f2tf32(v.z)); v.w = __uint_as_float(f2tf32(v.w));
    return v;
}
__device__ __forceinline__ void mma_tf32(float& c0, float& c1, float& c2, float& c3,
                                         uint32_t a0, uint32_t a1, uint32_t a2, uint32_t a3,
                                         uint32_t b0, uint32_t b1) {
    asm volatile("mma.sync.aligned.m16n8k8.row.col.f32.tf32.tf32.f32 "
                 "{%0,%1,%2,%3}, {%4,%5,%6,%7}, {%8,%9}, {%0,%1,%2,%3};"
                 : "+f"(c0), "+f"(c1), "+f"(c2), "+f"(c3)
                 : "r"(a0), "r"(a1), "r"(a2), "r"(a3), "r"(b0), "r"(b1));
}

// ---------------------------------------------------------------------------
// Weight transpose: in [R][C] row-major -> out [C][R] row-major
// ---------------------------------------------------------------------------
__global__ __launch_bounds__(256) void transpose_k(const float* __restrict__ in,
                                                   float* __restrict__ out, int R, int C)
{
    __shared__ float t[32][33];
    int bx = blockIdx.x * 32, by = blockIdx.y * 32;
#pragma unroll
    for (int i = 0; i < 32; i += 8)
        t[threadIdx.y + i][threadIdx.x] = in[(size_t)(by + threadIdx.y + i) * C + bx + threadIdx.x];
    __syncthreads();
#pragma unroll
    for (int i = 0; i < 32; i += 8)
        out[(size_t)(bx + threadIdx.y + i) * R + by + threadIdx.x] = t[threadIdx.x][threadIdx.y + i];
}

// ---------------------------------------------------------------------------
// tf32 GEMM via mma.sync: 128x128 tile, 64-wide K chunks, double-buffered.
// 8 warps (4m x 2n), warp = 32 x 64 = 2(m16) x 8(n8) mma tiles (64 accum regs).
// One __syncthreads per 64-K chunk; chunk s+1 LDG issued before compute of s,
// STS after compute into the other buffer.
// Per buffer (floats): A[128][68] + B[128][68] = 17408. Dyn smem = 139264 B.
// mode 0: scatter g_q(x0.125)/g_k [B,H,T,D]; g_v [B,H,D,T]. mode 1: C=acc+bias.
// ---------------------------------------------------------------------------
#define GPAD 68
#define GBUF (2 * 128 * GPAD)     // floats per buffer (A then B)
__global__ __launch_bounds__(256) void gemm_mma(
    const float* __restrict__ A, const float* __restrict__ Bt,
    const float* __restrict__ bias, float* __restrict__ C,
    int M, int N, int K, int mode)
{
    extern __shared__ float gsm[];

    const int tid  = threadIdx.x;
    const int wid  = tid >> 5;
    const int lane = tid & 31;
    const int g    = lane >> 2;
    const int t    = lane & 3;
    const int wm   = wid & 3;
    const int wn   = wid >> 2;
    const int m0 = blockIdx.y * 128;
    const int n0 = blockIdx.x * 128;

    const int lr = tid >> 4;          // 0..15 (row base, step 16)
    const int lk = (tid & 15) * 4;    // k offset 0..60

    float c[2][8][4];
#pragma unroll
    for (int mt = 0; mt < 2; ++mt)
#pragma unroll
        for (int nt = 0; nt < 8; ++nt)
#pragma unroll
            for (int j = 0; j < 4; ++j) c[mt][nt][j] = 0.f;

    float4 pa[8], pb[8];

    // prologue: chunk 0 -> buffer 0
#pragma unroll
    for (int i = 0; i < 8; ++i) {
        pa[i] = *(const float4*)(A + (size_t)(m0 + lr + i * 16) * K + lk);
        pb[i] = *(const float4*)(Bt + (size_t)(n0 + lr + i * 16) * K + lk);
    }
#pragma unroll
    for (int i = 0; i < 8; ++i) {
        *(float4*)&gsm[(lr + i * 16) * GPAD + lk] = cvt4(pa[i]);
        *(float4*)&gsm[128 * GPAD + (lr + i * 16) * GPAD + lk] = cvt4(pb[i]);
    }
    __syncthreads();

    const int KS = K >> 6;            // 64-wide chunks
#pragma unroll 1
    for (int s = 0; s < KS; ++s) {
        const float* As = gsm + (s & 1) * GBUF;
        const float* Bs = As + 128 * GPAD;

        if (s + 1 < KS) {
            const int k1 = ((s + 1) << 6) + lk;
#pragma unroll
            for (int i = 0; i < 8; ++i) {
                pa[i] = *(const float4*)(A + (size_t)(m0 + lr + i * 16) * K + k1);
                pb[i] = *(const float4*)(Bt + (size_t)(n0 + lr + i * 16) * K + k1);
            }
        }

#pragma unroll
        for (int kt = 0; kt < 8; ++kt) {
            const int kb = kt * 8;
            uint32_t bf[8][2];
#pragma unroll
            for (int nt = 0; nt < 8; ++nt) {
                int n = wn * 64 + nt * 8 + g;
                bf[nt][0] = __float_as_uint(Bs[n * GPAD + kb + t]);
                bf[nt][1] = __float_as_uint(Bs[n * GPAD + kb + t + 4]);
            }
#pragma unroll
            for (int mt = 0; mt < 2; ++mt) {
                int mb = wm * 32 + mt * 16;
                uint32_t a0 = __float_as_uint(As[(mb + g) * GPAD + kb + t]);
                uint32_t a1 = __float_as_uint(As[(mb + g + 8) * GPAD + kb + t]);
                uint32_t a2 = __float_as_uint(As[(mb + g) * GPAD + kb + t + 4]);
                uint32_t a3 = __float_as_uint(As[(mb + g + 8) * GPAD + kb + t + 4]);
#pragma unroll
                for (int nt = 0; nt < 8; ++nt)
                    mma_tf32(c[mt][nt][0], c[mt][nt][1], c[mt][nt][2], c[mt][nt][3],
                             a0, a1, a2, a3, bf[nt][0], bf[nt][1]);
            }
        }

        if (s + 1 < KS) {
            float* Ad = gsm + ((s + 1) & 1) * GBUF;
            float* Bd = Ad + 128 * GPAD;
#pragma unroll
            for (int i = 0; i < 8; ++i) {
                *(float4*)&Ad[(lr + i * 16) * GPAD + lk] = cvt4(pa[i]);
                *(float4*)&Bd[(lr + i * 16) * GPAD + lk] = cvt4(pb[i]);
            }
        }
        __syncthreads();
    }

    // Epilogue (warp covers 64 n-cols -> single which/head region in mode 0)
    const int nbase = n0 + wn * 64;
    if (mode == 0) {
        const int which = nbase >> 10;
        const int h = (nbase & 1023) >> 6;
#pragma unroll
        for (int mt = 0; mt < 2; ++mt) {
            int r0 = m0 + wm * 32 + mt * 16 + g;
            int bb0 = r0 >> 11, tt0 = r0 & (TSEQ - 1);
            int r1 = r0 + 8;
            int bb1 = r1 >> 11, tt1 = r1 & (TSEQ - 1);
            if (which == 2) {
                float* base0 = g_v + ((size_t)(bb0 * NHEAD + h)) * HSIZE * TSEQ;
                float* base1 = g_v + ((size_t)(bb1 * NHEAD + h)) * HSIZE * TSEQ;
#pragma unroll
                for (int nt = 0; nt < 8; ++nt) {
                    int d = nt * 8 + 2 * t;
                    base0[(size_t)d * TSEQ + tt0]       = c[mt][nt][0];
                    base0[(size_t)(d + 1) * TSEQ + tt0] = c[mt][nt][1];
                    base1[(size_t)d * TSEQ + tt1]       = c[mt][nt][2];
                    base1[(size_t)(d + 1) * TSEQ + tt1] = c[mt][nt][3];
                }
            } else {
                const float sc = (which == 0) ? 0.125f : 1.0f;
                float* base = (which == 0) ? g_q : g_k;
                float* d0 = base + (((size_t)(bb0 * NHEAD + h) * TSEQ) + tt0) * HSIZE;
                float* d1 = base + (((size_t)(bb1 * NHEAD + h) * TSEQ) + tt1) * HSIZE;
#pragma unroll
                for (int nt = 0; nt < 8; ++nt) {
                    int d = nt * 8 + 2 * t;
                    float2 v0 = {c[mt][nt][0] * sc, c[mt][nt][1] * sc};
                    float2 v1 = {c[mt][nt][2] * sc, c[mt][nt][3] * sc};
                    *(float2*)(d0 + d) = v0;
                    *(float2*)(d1 + d) = v1;
                }
            }
        }
    } else {
#pragma unroll
        for (int mt = 0; mt < 2; ++mt) {
            int r0 = m0 + wm * 32 + mt * 16 + g;
#pragma unroll
            for (int nt = 0; nt < 8; ++nt) {
                int n = nbase + nt * 8 + 2 * t;
                float2 bv = *(const float2*)(bias + n);
                float2 v0 = {c[mt][nt][0] + bv.x, c[mt][nt][1] + bv.y};
                float2 v1 = {c[mt][nt][2] + bv.x, c[mt][nt][3] + bv.y};
                *(float2*)(C + (size_t)r0 * N + n) = v0;
                *(float2*)(C + (size_t)(r0 + 8) * N + n) = v1;
            }
        }
    }
}

// ---------------------------------------------------------------------------
// Tensor-core causal flash attention (tf32 mma.sync), 128-key tiles,
// DOUBLE-BUFFERED KV with split prefetch:
//   K(jt+1) LDG before S-mma, STS after; V(jt+1) LDG before PV-mma, STS after.
//   One __syncthreads per tile.
// Smem: QP [128][132] (Q stage, then P), 2 x { Ks[128][68], Vs[64][132] }.
// Dyn smem = (16896 + 2*17152)*4 = 204800 B.
// ---------------------------------------------------------------------------
#define QP_PAD 132
#define K_PAD  68
#define KVBUF  (128 * K_PAD + 64 * QP_PAD)   // floats per KV buffer
__global__ __launch_bounds__(256) void attn_mma()
{
    extern __shared__ float sm[];
    float* Qs  = sm;                          // [128][QP_PAD] (aliased by Ps)
    float* KV0 = sm + 128 * QP_PAD;
    float* Ps  = Qs;

    const int tid  = threadIdx.x;
    const int wid  = tid >> 5;
    const int lane = tid & 31;
    const int g    = lane >> 2;
    const int t    = lane & 3;
    const int mb   = wid * 16;
    const int bh   = blockIdx.y;
    const int qb   = gridDim.x - 1 - blockIdx.x;   // heavy CTAs first
    const int q0   = qb * 128;

    // stage Q tile [128][64] -> smem (tf32-rounded)
    const float* Qg = g_q + ((size_t)bh * TSEQ + q0) * HSIZE;
#pragma unroll
    for (int i = 0; i < 8; ++i) {
        int f = tid + i * 256;
        int r = f >> 4, c4 = (f & 15) * 4;
        *(float4*)&Qs[r * QP_PAD + c4] = cvt4(*(const float4*)(Qg + (size_t)r * HSIZE + c4));
    }
    __syncthreads();

    uint32_t qa[8][4];
#pragma unroll
    for (int kb = 0; kb < 8; ++kb) {
        qa[kb][0] = __float_as_uint(Qs[(mb + g) * QP_PAD + kb * 8 + t]);
        qa[kb][1] = __float_as_uint(Qs[(mb + g + 8) * QP_PAD + kb * 8 + t]);
        qa[kb][2] = __float_as_uint(Qs[(mb + g) * QP_PAD + kb * 8 + t + 4]);
        qa[kb][3] = __float_as_uint(Qs[(mb + g + 8) * QP_PAD + kb * 8 + t + 4]);
    }
    __syncthreads();   // Qs free for P reuse

    float o[8][4];
#pragma unroll
    for (int nt = 0; nt < 8; ++nt)
#pragma unroll
        for (int j = 0; j < 4; ++j) o[nt][j] = 0.f;
    float m0 = -INFINITY, m1 = -INFINITY, l0 = 0.f, l1 = 0.f;

    const int row0 = q0 + mb + g;
    const int row1 = row0 + 8;

    const float* Kg = g_k + (size_t)bh * TSEQ * HSIZE;
    const float* Vg = g_v + (size_t)bh * HSIZE * TSEQ;

    // loader indices
    const int kr = tid >> 4, kc = (tid & 15) * 4;   // K: 16 rows/iter, 64 k
    const int vr = tid >> 5, vc = (tid & 31) * 4;   // V: 8 rows/iter, 128 k

    // prologue: tile 0 -> buffer 0
    {
        float* Ks0 = KV0;
        float* Vs0 = KV0 + 128 * K_PAD;
#pragma unroll
        for (int i = 0; i < 8; ++i) {
            *(float4*)&Ks0[(kr + i * 16) * K_PAD + kc] =
                cvt4(*(const float4*)(Kg + (size_t)(kr + i * 16) * HSIZE + kc));
            *(float4*)&Vs0[(vr + i * 8) * QP_PAD + vc] =
                cvt4(*(const float4*)(Vg + (size_t)(vr + i * 8) * TSEQ + vc));
        }
    }
    __syncthreads();

    for (int jt = 0; jt <= qb; ++jt) {
        const int cur = jt & 1;
        const float* Ksc = KV0 + cur * KVBUF;
        const float* Vsc = Ksc + 128 * K_PAD;
        float* Ksn = KV0 + (1 - cur) * KVBUF;
        float* Vsn = Ksn + 128 * K_PAD;
        const bool pre = (jt < qb);

        // prefetch K(jt+1)
        float4 pk[8];
        if (pre) {
#pragma unroll
            for (int i = 0; i < 8; ++i)
                pk[i] = *(const float4*)(Kg + (size_t)((jt + 1) * 128 + kr + i * 16) * HSIZE + kc);
        }

        // S = Q K^T
        float s[16][4];
#pragma unroll
        for (int nt = 0; nt < 16; ++nt)
#pragma unroll
            for (int j = 0; j < 4; ++j) s[nt][j] = 0.f;
#pragma unroll
        for (int kb = 0; kb < 8; ++kb) {
#pragma unroll
            for (int nt = 0; nt < 16; ++nt) {
                int n = nt * 8 + g;
                uint32_t b0 = __float_as_uint(Ksc[n * K_PAD + kb * 8 + t]);
                uint32_t b1 = __float_as_uint(Ksc[n * K_PAD + kb * 8 + t + 4]);
                mma_tf32(s[nt][0], s[nt][1], s[nt][2], s[nt][3],
                         qa[kb][0], qa[kb][1], qa[kb][2], qa[kb][3], b0, b1);
            }
        }

        // store prefetched K
        if (pre) {
#pragma unroll
            for (int i = 0; i < 8; ++i)
                *(float4*)&Ksn[(kr + i * 16) * K_PAD + kc] = cvt4(pk[i]);
        }

        // causal mask on diagonal tile
        if (jt == qb) {
#pragma unroll
            for (int nt = 0; nt < 16; ++nt) {
                int col = jt * 128 + nt * 8 + 2 * t;
                if (col > row0)     s[nt][0] = -INFINITY;
                if (col + 1 > row0) s[nt][1] = -INFINITY;
                if (col > row1)     s[nt][2] = -INFINITY;
                if (col + 1 > row1) s[nt][3] = -INFINITY;
            }
        }

        // online softmax
        float mx0 = -INFINITY, mx1 = -INFINITY;
#pragma unroll
        for (int nt = 0; nt < 16; ++nt) {
            mx0 = fmaxf(mx0, fmaxf(s[nt][0], s[nt][1]));
            mx1 = fmaxf(mx1, fmaxf(s[nt][2], s[nt][3]));
        }
        mx0 = fmaxf(mx0, __shfl_xor_sync(0xffffffffu, mx0, 1));
        mx0 = fmaxf(mx0, __shfl_xor_sync(0xffffffffu, mx0, 2));
        mx1 = fmaxf(mx1, __shfl_xor_sync(0xffffffffu, mx1, 1));
        mx1 = fmaxf(mx1, __shfl_xor_sync(0xffffffffu, mx1, 2));
        float nm0 = fmaxf(m0, mx0), nm1 = fmaxf(m1, mx1);
        float cr0 = __expf(m0 - nm0), cr1 = __expf(m1 - nm1);
        l0 *= cr0; l1 *= cr1;
#pragma unroll
        for (int nt = 0; nt < 8; ++nt) {
            o[nt][0] *= cr0; o[nt][1] *= cr0;
            o[nt][2] *= cr1; o[nt][3] *= cr1;
        }
        float s0 = 0.f, s1 = 0.f;
#pragma unroll
        for (int nt = 0; nt < 16; ++nt) {
            float p00 = __expf(s[nt][0] - nm0);
            float p01 = __expf(s[nt][1] - nm0);
            float p10 = __expf(s[nt][2] - nm1);
            float p11 = __expf(s[nt][3] - nm1);
            s0 += p00 + p01; s1 += p10 + p11;
            float2 w0 = {__uint_as_float(f2tf32(p00)), __uint_as_float(f2tf32(p01))};
            float2 w1 = {__uint_as_float(f2tf32(p10)), __uint_as_float(f2tf32(p11))};
            *(float2*)&Ps[(mb + g) * QP_PAD + nt * 8 + 2 * t] = w0;
            *(float2*)&Ps[(mb + g + 8) * QP_PAD + nt * 8 + 2 * t] = w1;
        }
        s0 += __shfl_xor_sync(0xffffffffu, s0, 1);
        s0 += __shfl_xor_sync(0xffffffffu, s0, 2);
        s1 += __shfl_xor_sync(0xffffffffu, s1, 1);
        s1 += __shfl_xor_sync(0xffffffffu, s1, 2);
        l0 += s0; l1 += s1;
        m0 = nm0; m1 = nm1;
        __syncwarp();

        // prefetch V(jt+1)
        float4 pv[8];
        if (pre) {
#pragma unroll
            for (int i = 0; i < 8; ++i)
                pv[i] = *(const float4*)(Vg + (size_t)(vr + i * 8) * TSEQ + (jt + 1) * 128 + vc);
        }

        // O += P V
#pragma unroll
        for (int kb = 0; kb < 16; ++kb) {
            uint32_t pa0 = __float_as_uint(Ps[(mb + g) * QP_PAD + kb * 8 + t]);
            uint32_t pa1 = __float_as_uint(Ps[(mb + g + 8) * QP_PAD + kb * 8 + t]);
            uint32_t pa2 = __float_as_uint(Ps[(mb + g) * QP_PAD + kb * 8 + t + 4]);
            uint32_t pa3 = __float_as_uint(Ps[(mb + g + 8) * QP_PAD + kb * 8 + t + 4]);
#pragma unroll
            for (int nt = 0; nt < 8; ++nt) {
                int n = nt * 8 + g;
                uint32_t b0 = __float_as_uint(Vsc[n * QP_PAD + kb * 8 + t]);
                uint32_t b1 = __float_as_uint(Vsc[n * QP_PAD + kb * 8 + t + 4]);
                mma_tf32(o[nt][0], o[nt][1], o[nt][2], o[nt][3],
                         pa0, pa1, pa2, pa3, b0, b1);
            }
        }

        // store prefetched V
        if (pre) {
#pragma unroll
            for (int i = 0; i < 8; ++i)
                *(float4*)&Vsn[(vr + i * 8) * QP_PAD + vc] = cvt4(pv[i]);
        }
        __syncthreads();   // one sync per tile
    }

    const int b = bh >> 4, h = bh & 15;
    const float inv0 = 1.f / l0, inv1 = 1.f / l1;
    float* O0 = g_attn + ((size_t)(b * TSEQ) + row0) * CEMB + h * HSIZE;
    float* O1 = g_attn + ((size_t)(b * TSEQ) + row1) * CEMB + h * HSIZE;
#pragma unroll
    for (int nt = 0; nt < 8; ++nt) {
        int d = nt * 8 + 2 * t;
        float2 v0 = {o[nt][0] * inv0, o[nt][1] * inv0};
        float2 v1 = {o[nt][2] * inv1, o[nt][3] * inv1};
        *(float2*)(O0 + d) = v0;
        *(float2*)(O1 + d) = v1;
    }
}

// ---------------------------------------------------------------------------
extern "C" void kernel_launch(void* const* d_in, const int* in_sizes, int n_in,
                              void* d_out, int out_size)
{
    const float* x      = (const float*)d_in[0];
    const float* w_qkv  = (const float*)d_in[1];
    const float* w_proj = (const float*)d_in[2];
    const float* b_proj = (const float*)d_in[3];
    float* out = (float*)d_out;

    float *attn_ptr = nullptr, *wtq = nullptr, *wtp = nullptr;
    cudaGetSymbolAddress((void**)&attn_ptr, g_attn);
    cudaGetSymbolAddress((void**)&wtq, g_wt_qkv);
    cudaGetSymbolAddress((void**)&wtp, g_wt_proj);

    const int ATTN_SMEM = (128 * QP_PAD + 2 * KVBUF) * 4;   // 204800
    const int GEMM_SMEM = 2 * GBUF * 4;                     // 139264
    cudaFuncSetAttribute(attn_mma, cudaFuncAttributeMaxDynamicSharedMemorySize, ATTN_SMEM);
    cudaFuncSetAttribute(gemm_mma, cudaFuncAttributeMaxDynamicSharedMemorySize, GEMM_SMEM);

    // 0) transpose weights to K-major
    transpose_k<<<dim3(3 * CEMB / 32, CEMB / 32), dim3(32, 8)>>>(w_qkv, wtq, CEMB, 3 * CEMB);
    transpose_k<<<dim3(CEMB / 32, CEMB / 32), dim3(32, 8)>>>(w_proj, wtp, CEMB, CEMB);

    // 1) QKV GEMM + head-major scatter (V transposed)
    gemm_mma<<<dim3(3 * CEMB / 128, MROWS / 128), 256, GEMM_SMEM>>>(
        x, wtq, nullptr, nullptr, MROWS, 3 * CEMB, CEMB, 0);

    // 2) Causal flash attention (tf32 mma, double-buffered KV)
    attn_mma<<<dim3(TSEQ / 128, BATCH * NHEAD), 256, ATTN_SMEM>>>();

    // 3) Output projection + bias
    gemm_mma<<<dim3(CEMB / 128, MROWS / 128), 256, GEMM_SMEM>>>(
        attn_ptr, wtp, b_proj, out, MROWS, CEMB, CEMB, 1);
}

// round 8
// speedup vs baseline: 1.0685x; 1.0685x over previous
#include <cuda_runtime.h>
#include <math.h>
#include <stdint.h>

// Problem constants
#define BATCH   4
#define TSEQ    2048
#define NHEAD   16
#define HSIZE   64
#define CEMB    1024
#define MROWS   (BATCH*TSEQ)   // 8192

// Scratch (device globals: allocation-free rule)
__device__ float g_q[(size_t)BATCH * NHEAD * TSEQ * HSIZE];   // [B,H,T,D], q pre-scaled
__device__ float g_k[(size_t)BATCH * NHEAD * TSEQ * HSIZE];   // [B,H,T,D]
__device__ float g_v[(size_t)BATCH * NHEAD * TSEQ * HSIZE];   // [B,H,D,T]  (transposed!)
__device__ float g_attn[(size_t)MROWS * CEMB];                // [B*T, C]
__device__ float g_wt_qkv[(size_t)3 * CEMB * CEMB];           // [3C, C] K-major
__device__ float g_wt_proj[(size_t)CEMB * CEMB];              // [C, C]  K-major

// ---------------------------------------------------------------------------
// tf32 helpers
// ---------------------------------------------------------------------------
__device__ __forceinline__ uint32_t f2tf32(float x) {
    uint32_t r;
    asm("cvt.rna.tf32.f32 %0, %1;" : "=r"(r) : "f"(x));
    return r;
}
__device__ __forceinline__ float4 cvt4(float4 v) {
    v.x = __uint_as_float(f2tf32(v.x)); v.y = __uint_as_float(f2tf32(v.y));
    v.z = __uint_as_float(f2tf32(v.z)); v.w = __uint_as_float(f2tf32(v.w));
    return v;
}
__device__ __forceinline__ void mma_tf32(float& c0, float& c1, float& c2, float& c3,
                                         uint32_t a0, uint32_t a1, uint32_t a2, uint32_t a3,
                                         uint32_t b0, uint32_t b1) {
    asm volatile("mma.sync.aligned.m16n8k8.row.col.f32.tf32.tf32.f32 "
                 "{%0,%1,%2,%3}, {%4,%5,%6,%7}, {%8,%9}, {%0,%1,%2,%3};"
                 : "+f"(c0), "+f"(c1), "+f"(c2), "+f"(c3)
                 : "r"(a0), "r"(a1), "r"(a2), "r"(a3), "r"(b0), "r"(b1));
}

// ---------------------------------------------------------------------------
// Weight transpose
// ---------------------------------------------------------------------------
__global__ __launch_bounds__(256) void transpose_k(const float* __restrict__ in,
                                                   float* __restrict__ out, int R, int C)
{
    __shared__ float t[32][33];
    int bx = blockIdx.x * 32, by = blockIdx.y * 32;
#pragma unroll
    for (int i = 0; i < 32; i += 8)
        t[threadIdx.y + i][threadIdx.x] = in[(size_t)(by + threadIdx.y + i) * C + bx + threadIdx.x];
    __syncthreads();
#pragma unroll
    for (int i = 0; i < 32; i += 8)
        out[(size_t)(bx + threadIdx.y + i) * R + by + threadIdx.x] = t[threadIdx.x][threadIdx.y + i];
}

// ---------------------------------------------------------------------------
// tf32 GEMM (round-6 version, measured best): 128(M)x256(N) tile,
// double-buffered 32-wide K chunks, LDG before compute / STS after.
// ---------------------------------------------------------------------------
#define GA_OFF 0
#define GB_OFF 4608
#define GBUF_STRIDE 13824
__global__ __launch_bounds__(256) void gemm_mma(
    const float* __restrict__ A, const float* __restrict__ Bt,
    const float* __restrict__ bias, float* __restrict__ C,
    int M, int N, int K, int mode)
{
    extern __shared__ float gsm[];

    const int tid  = threadIdx.x;
    const int wid  = tid >> 5;
    const int lane = tid & 31;
    const int g    = lane >> 2;
    const int t    = lane & 3;
    const int wm   = wid & 3;
    const int wn   = wid >> 2;
    const int m0 = blockIdx.y * 128;
    const int n0 = blockIdx.x * 256;

    const int lr = tid >> 3;
    const int lk = (tid & 7) * 4;

    float c[2][16][4];
#pragma unroll
    for (int mt = 0; mt < 2; ++mt)
#pragma unroll
        for (int nt = 0; nt < 16; ++nt)
#pragma unroll
            for (int j = 0; j < 4; ++j) c[mt][nt][j] = 0.f;

    float4 pa[4], pb[8];

#pragma unroll
    for (int i = 0; i < 4; ++i)
        pa[i] = *(const float4*)(A + (size_t)(m0 + lr + i * 32) * K + lk);
#pragma unroll
    for (int i = 0; i < 8; ++i)
        pb[i] = *(const float4*)(Bt + (size_t)(n0 + lr + i * 32) * K + lk);
#pragma unroll
    for (int i = 0; i < 4; ++i)
        *(float4*)&gsm[GA_OFF + (lr + i * 32) * 36 + lk] = cvt4(pa[i]);
#pragma unroll
    for (int i = 0; i < 8; ++i)
        *(float4*)&gsm[GB_OFF + (lr + i * 32) * 36 + lk] = cvt4(pb[i]);
    __syncthreads();

    const int KS = K >> 5;
#pragma unroll 1
    for (int s = 0; s < KS; ++s) {
        const float* As = gsm + (s & 1) * GBUF_STRIDE + GA_OFF;
        const float* Bs = gsm + (s & 1) * GBUF_STRIDE + GB_OFF;

        if (s + 1 < KS) {
            const int k1 = (s + 1) << 5;
#pragma unroll
            for (int i = 0; i < 4; ++i)
                pa[i] = *(const float4*)(A + (size_t)(m0 + lr + i * 32) * K + k1 + lk);
#pragma unroll
            for (int i = 0; i < 8; ++i)
                pb[i] = *(const float4*)(Bt + (size_t)(n0 + lr + i * 32) * K + k1 + lk);
        }

#pragma unroll
        for (int kt = 0; kt < 4; ++kt) {
            const int kb = kt * 8;
            uint32_t bf[16][2];
#pragma unroll
            for (int nt = 0; nt < 16; ++nt) {
                int n = wn * 128 + nt * 8 + g;
                bf[nt][0] = __float_as_uint(Bs[n * 36 + kb + t]);
                bf[nt][1] = __float_as_uint(Bs[n * 36 + kb + t + 4]);
            }
#pragma unroll
            for (int mt = 0; mt < 2; ++mt) {
                int mb = wm * 32 + mt * 16;
                uint32_t a0 = __float_as_uint(As[(mb + g) * 36 + kb + t]);
                uint32_t a1 = __float_as_uint(As[(mb + g + 8) * 36 + kb + t]);
                uint32_t a2 = __float_as_uint(As[(mb + g) * 36 + kb + t + 4]);
                uint32_t a3 = __float_as_uint(As[(mb + g + 8) * 36 + kb + t + 4]);
#pragma unroll
                for (int nt = 0; nt < 16; ++nt)
                    mma_tf32(c[mt][nt][0], c[mt][nt][1], c[mt][nt][2], c[mt][nt][3],
                             a0, a1, a2, a3, bf[nt][0], bf[nt][1]);
            }
        }

        if (s + 1 < KS) {
            float* Ad = gsm + ((s + 1) & 1) * GBUF_STRIDE + GA_OFF;
            float* Bd = gsm + ((s + 1) & 1) * GBUF_STRIDE + GB_OFF;
#pragma unroll
            for (int i = 0; i < 4; ++i)
                *(float4*)&Ad[(lr + i * 32) * 36 + lk] = cvt4(pa[i]);
#pragma unroll
            for (int i = 0; i < 8; ++i)
                *(float4*)&Bd[(lr + i * 32) * 36 + lk] = cvt4(pb[i]);
        }
        __syncthreads();
    }

    const int nwarp = n0 + wn * 128;
    if (mode == 0) {
#pragma unroll
        for (int mt = 0; mt < 2; ++mt) {
            int r0 = m0 + wm * 32 + mt * 16 + g;
            int bb0 = r0 >> 11, tt0 = r0 & (TSEQ - 1);
            int r1 = r0 + 8;
            int bb1 = r1 >> 11, tt1 = r1 & (TSEQ - 1);
#pragma unroll
            for (int nt = 0; nt < 16; ++nt) {
                int n = nwarp + nt * 8;
                int which = n >> 10;
                int h = (n & 1023) >> 6;
                int d = (n & 63) + 2 * t;
                if (which == 2) {
                    float* base0 = g_v + ((size_t)(bb0 * NHEAD + h)) * HSIZE * TSEQ;
                    float* base1 = g_v + ((size_t)(bb1 * NHEAD + h)) * HSIZE * TSEQ;
                    base0[(size_t)d * TSEQ + tt0]       = c[mt][nt][0];
                    base0[(size_t)(d + 1) * TSEQ + tt0] = c[mt][nt][1];
                    base1[(size_t)d * TSEQ + tt1]       = c[mt][nt][2];
                    base1[(size_t)(d + 1) * TSEQ + tt1] = c[mt][nt][3];
                } else {
                    const float sc = (which == 0) ? 0.125f : 1.0f;
                    float* base = (which == 0) ? g_q : g_k;
                    float* d0 = base + (((size_t)(bb0 * NHEAD + h) * TSEQ) + tt0) * HSIZE + d;
                    float* d1 = base + (((size_t)(bb1 * NHEAD + h) * TSEQ) + tt1) * HSIZE + d;
                    float2 v0 = {c[mt][nt][0] * sc, c[mt][nt][1] * sc};
                    float2 v1 = {c[mt][nt][2] * sc, c[mt][nt][3] * sc};
                    *(float2*)d0 = v0;
                    *(float2*)d1 = v1;
                }
            }
        }
    } else {
#pragma unroll
        for (int mt = 0; mt < 2; ++mt) {
            int r0 = m0 + wm * 32 + mt * 16 + g;
#pragma unroll
            for (int nt = 0; nt < 16; ++nt) {
                int n = nwarp + nt * 8 + 2 * t;
                float2 bv = *(const float2*)(bias + n);
                float2 v0 = {c[mt][nt][0] + bv.x, c[mt][nt][1] + bv.y};
                float2 v1 = {c[mt][nt][2] + bv.x, c[mt][nt][3] + bv.y};
                *(float2*)(C + (size_t)r0 * N + n) = v0;
                *(float2*)(C + (size_t)(r0 + 8) * N + n) = v1;
            }
        }
    }
}

// ---------------------------------------------------------------------------
// Tensor-core causal flash attention (tf32 mma.sync), 128-key tiles,
// FRAGMENT-PACKED K/V smem: pair (k=t, k=t+4) stored adjacent -> LDS.64 per
// B-fragment (halves B-frag LDS). XOR swizzles keep both the repacking STS
// and the fragment LDS bank-conflict-free (pads == 8 mod 32).
//   K: [128][72]  packed, inner^= ((kb>>2)&1)<<2
//   V: [64][136]  packed, inner^= ((kb>>2)&3)<<1
// Q/P buffer unchanged ([128][132]). Single KV buffer, 2 syncs/tile.
// Dyn smem = (128*132 + 128*72 + 64*136)*4 = 139264 B.
// ---------------------------------------------------------------------------
#define QP_PAD 132
#define KPP    72
#define VPP    136
__global__ __launch_bounds__(256) void attn_mma()
{
    extern __shared__ float sm[];
    float* Qs = sm;                        // [128][QP_PAD] (aliased by Ps)
    float* Ks = sm + 128 * QP_PAD;         // [128][KPP] packed
    float* Vs = Ks + 128 * KPP;            // [64][VPP] packed
    float* Ps = Qs;

    const int tid  = threadIdx.x;
    const int wid  = tid >> 5;
    const int lane = tid & 31;
    const int g    = lane >> 2;
    const int t    = lane & 3;
    const int mb   = wid * 16;
    const int bh   = blockIdx.y;
    const int qb   = gridDim.x - 1 - blockIdx.x;   // heavy CTAs first
    const int q0   = qb * 128;

    // stage Q tile [128][64] -> smem (tf32-rounded), plain layout
    const float* Qg = g_q + ((size_t)bh * TSEQ + q0) * HSIZE;
#pragma unroll
    for (int i = 0; i < 8; ++i) {
        int f = tid + i * 256;
        int r = f >> 4, c4 = (f & 15) * 4;
        *(float4*)&Qs[r * QP_PAD + c4] = cvt4(*(const float4*)(Qg + (size_t)r * HSIZE + c4));
    }
    __syncthreads();

    uint32_t qa[8][4];
#pragma unroll
    for (int kb = 0; kb < 8; ++kb) {
        qa[kb][0] = __float_as_uint(Qs[(mb + g) * QP_PAD + kb * 8 + t]);
        qa[kb][1] = __float_as_uint(Qs[(mb + g + 8) * QP_PAD + kb * 8 + t]);
        qa[kb][2] = __float_as_uint(Qs[(mb + g) * QP_PAD + kb * 8 + t + 4]);
        qa[kb][3] = __float_as_uint(Qs[(mb + g + 8) * QP_PAD + kb * 8 + t + 4]);
    }
    __syncthreads();   // Qs free for P reuse

    float o[8][4];
#pragma unroll
    for (int nt = 0; nt < 8; ++nt)
#pragma unroll
        for (int j = 0; j < 4; ++j) o[nt][j] = 0.f;
    float m0 = -INFINITY, m1 = -INFINITY, l0 = 0.f, l1 = 0.f;

    const int row0 = q0 + mb + g;
    const int row1 = row0 + 8;

    const float* Kg = g_k + (size_t)bh * TSEQ * HSIZE;
    const float* Vg = g_v + (size_t)bh * HSIZE * TSEQ;

    // loader indices
    const int kr = tid >> 4, kc = (tid & 15) * 4;   // K: row kr+16i, cols kc..kc+3
    const int vr = tid >> 5, vc = (tid & 31) * 4;   // V: row vr+8i, cols vc..vc+3
    // packing constants (warp-uniform per thread)
    const int kkb = kc >> 3, khi = (kc & 7) >> 2;
    const int kx  = ((kkb >> 2) & 1) << 2;
    const int vkb = vc >> 3, vhi = (vc & 7) >> 2;
    const int vx  = ((vkb >> 2) & 3) << 1;

    for (int jt = 0; jt <= qb; ++jt) {
        // --- load & repack K, V tiles ---
#pragma unroll
        for (int i = 0; i < 8; ++i) {
            float4 kv = cvt4(*(const float4*)(Kg + (size_t)(jt * 128 + kr + i * 16) * HSIZE + kc));
            float* kd = &Ks[(kr + i * 16) * KPP + kkb * 8];
            kd[((0 << 1) | khi) ^ kx] = kv.x;
            kd[((1 << 1) | khi) ^ kx] = kv.y;
            kd[((2 << 1) | khi) ^ kx] = kv.z;
            kd[((3 << 1) | khi) ^ kx] = kv.w;
            float4 vv = cvt4(*(const float4*)(Vg + (size_t)(vr + i * 8) * TSEQ + jt * 128 + vc));
            float* vd = &Vs[(vr + i * 8) * VPP + vkb * 8];
            vd[((0 << 1) | vhi) ^ vx] = vv.x;
            vd[((1 << 1) | vhi) ^ vx] = vv.y;
            vd[((2 << 1) | vhi) ^ vx] = vv.z;
            vd[((3 << 1) | vhi) ^ vx] = vv.w;
        }
        __syncthreads();

        // --- S = Q K^T (B-frags via LDS.64) ---
        float s[16][4];
#pragma unroll
        for (int nt = 0; nt < 16; ++nt)
#pragma unroll
            for (int j = 0; j < 4; ++j) s[nt][j] = 0.f;
#pragma unroll
        for (int kb = 0; kb < 8; ++kb) {
            const int koff = kb * 8 + ((2 * t) ^ (((kb >> 2) & 1) << 2));
#pragma unroll
            for (int nt = 0; nt < 16; ++nt) {
                int n = nt * 8 + g;
                float2 bp = *(const float2*)&Ks[n * KPP + koff];
                mma_tf32(s[nt][0], s[nt][1], s[nt][2], s[nt][3],
                         qa[kb][0], qa[kb][1], qa[kb][2], qa[kb][3],
                         __float_as_uint(bp.x), __float_as_uint(bp.y));
            }
        }

        // causal mask on diagonal tile
        if (jt == qb) {
#pragma unroll
            for (int nt = 0; nt < 16; ++nt) {
                int col = jt * 128 + nt * 8 + 2 * t;
                if (col > row0)     s[nt][0] = -INFINITY;
                if (col + 1 > row0) s[nt][1] = -INFINITY;
                if (col > row1)     s[nt][2] = -INFINITY;
                if (col + 1 > row1) s[nt][3] = -INFINITY;
            }
        }

        // --- online softmax ---
        float mx0 = -INFINITY, mx1 = -INFINITY;
#pragma unroll
        for (int nt = 0; nt < 16; ++nt) {
            mx0 = fmaxf(mx0, fmaxf(s[nt][0], s[nt][1]));
            mx1 = fmaxf(mx1, fmaxf(s[nt][2], s[nt][3]));
        }
        mx0 = fmaxf(mx0, __shfl_xor_sync(0xffffffffu, mx0, 1));
        mx0 = fmaxf(mx0, __shfl_xor_sync(0xffffffffu, mx0, 2));
        mx1 = fmaxf(mx1, __shfl_xor_sync(0xffffffffu, mx1, 1));
        mx1 = fmaxf(mx1, __shfl_xor_sync(0xffffffffu, mx1, 2));
        float nm0 = fmaxf(m0, mx0), nm1 = fmaxf(m1, mx1);
        float cr0 = __expf(m0 - nm0), cr1 = __expf(m1 - nm1);
        l0 *= cr0; l1 *= cr1;
#pragma unroll
        for (int nt = 0; nt < 8; ++nt) {
            o[nt][0] *= cr0; o[nt][1] *= cr0;
            o[nt][2] *= cr1; o[nt][3] *= cr1;
        }
        float s0 = 0.f, s1 = 0.f;
#pragma unroll
        for (int nt = 0; nt < 16; ++nt) {
            float p00 = __expf(s[nt][0] - nm0);
            float p01 = __expf(s[nt][1] - nm0);
            float p10 = __expf(s[nt][2] - nm1);
            float p11 = __expf(s[nt][3] - nm1);
            s0 += p00 + p01; s1 += p10 + p11;
            float2 w0 = {__uint_as_float(f2tf32(p00)), __uint_as_float(f2tf32(p01))};
            float2 w1 = {__uint_as_float(f2tf32(p10)), __uint_as_float(f2tf32(p11))};
            *(float2*)&Ps[(mb + g) * QP_PAD + nt * 8 + 2 * t] = w0;
            *(float2*)&Ps[(mb + g + 8) * QP_PAD + nt * 8 + 2 * t] = w1;
        }
        s0 += __shfl_xor_sync(0xffffffffu, s0, 1);
        s0 += __shfl_xor_sync(0xffffffffu, s0, 2);
        s1 += __shfl_xor_sync(0xffffffffu, s1, 1);
        s1 += __shfl_xor_sync(0xffffffffu, s1, 2);
        l0 += s0; l1 += s1;
        m0 = nm0; m1 = nm1;
        __syncwarp();

        // --- O += P V (B-frags via LDS.64) ---
#pragma unroll
        for (int kb = 0; kb < 16; ++kb) {
            uint32_t pa0 = __float_as_uint(Ps[(mb + g) * QP_PAD + kb * 8 + t]);
            uint32_t pa1 = __float_as_uint(Ps[(mb + g + 8) * QP_PAD + kb * 8 + t]);
            uint32_t pa2 = __float_as_uint(Ps[(mb + g) * QP_PAD + kb * 8 + t + 4]);
            uint32_t pa3 = __float_as_uint(Ps[(mb + g + 8) * QP_PAD + kb * 8 + t + 4]);
            const int voff = kb * 8 + ((2 * t) ^ (((kb >> 2) & 3) << 1));
#pragma unroll
            for (int nt = 0; nt < 8; ++nt) {
                int n = nt * 8 + g;
                float2 bp = *(const float2*)&Vs[n * VPP + voff];
                mma_tf32(o[nt][0], o[nt][1], o[nt][2], o[nt][3],
                         pa0, pa1, pa2, pa3,
                         __float_as_uint(bp.x), __float_as_uint(bp.y));
            }
        }
        __syncthreads();   // Ks/Vs/Ps reuse next tile
    }

    const int b = bh >> 4, h = bh & 15;
    const float inv0 = 1.f / l0, inv1 = 1.f / l1;
    float* O0 = g_attn + ((size_t)(b * TSEQ) + row0) * CEMB + h * HSIZE;
    float* O1 = g_attn + ((size_t)(b * TSEQ) + row1) * CEMB + h * HSIZE;
#pragma unroll
    for (int nt = 0; nt < 8; ++nt) {
        int d = nt * 8 + 2 * t;
        float2 v0 = {o[nt][0] * inv0, o[nt][1] * inv0};
        float2 v1 = {o[nt][2] * inv1, o[nt][3] * inv1};
        *(float2*)(O0 + d) = v0;
        *(float2*)(O1 + d) = v1;
    }
}

// ---------------------------------------------------------------------------
extern "C" void kernel_launch(void* const* d_in, const int* in_sizes, int n_in,
                              void* d_out, int out_size)
{
    const float* x      = (const float*)d_in[0];
    const float* w_qkv  = (const float*)d_in[1];
    const float* w_proj = (const float*)d_in[2];
    const float* b_proj = (const float*)d_in[3];
    float* out = (float*)d_out;

    float *attn_ptr = nullptr, *wtq = nullptr, *wtp = nullptr;
    cudaGetSymbolAddress((void**)&attn_ptr, g_attn);
    cudaGetSymbolAddress((void**)&wtq, g_wt_qkv);
    cudaGetSymbolAddress((void**)&wtp, g_wt_proj);

    const int ATTN_SMEM = (128 * QP_PAD + 128 * KPP + 64 * VPP) * 4;  // 139264
    const int GEMM_SMEM = 2 * GBUF_STRIDE * 4;                        // 110592
    cudaFuncSetAttribute(attn_mma, cudaFuncAttributeMaxDynamicSharedMemorySize, ATTN_SMEM);
    cudaFuncSetAttribute(gemm_mma, cudaFuncAttributeMaxDynamicSharedMemorySize, GEMM_SMEM);

    // 0) transpose weights to K-major
    transpose_k<<<dim3(3 * CEMB / 32, CEMB / 32), dim3(32, 8)>>>(w_qkv, wtq, CEMB, 3 * CEMB);
    transpose_k<<<dim3(CEMB / 32, CEMB / 32), dim3(32, 8)>>>(w_proj, wtp, CEMB, CEMB);

    // 1) QKV GEMM + head-major scatter (V transposed)
    gemm_mma<<<dim3(3 * CEMB / 256, MROWS / 128), 256, GEMM_SMEM>>>(
        x, wtq, nullptr, nullptr, MROWS, 3 * CEMB, CEMB, 0);

    // 2) Causal flash attention (tf32 mma, fragment-packed K/V)
    attn_mma<<<dim3(TSEQ / 128, BATCH * NHEAD), 256, ATTN_SMEM>>>();

    // 3) Output projection + bias
    gemm_mma<<<dim3(CEMB / 256, MROWS / 128), 256, GEMM_SMEM>>>(
        attn_ptr, wtp, b_proj, out, MROWS, CEMB, CEMB, 1);
}

// round 9
// speedup vs baseline: 1.9686x; 1.8423x over previous
#include <cuda_runtime.h>
#include <cuda_fp16.h>
#include <math.h>
#include <stdint.h>

// Problem constants
#define BATCH   4
#define TSEQ    2048
#define NHEAD   16
#define HSIZE   64
#define CEMB    1024
#define MROWS   (BATCH*TSEQ)   // 8192

// Scratch (device globals; all fp16 operands, fp32 accum everywhere)
__device__ __half g_xh [(size_t)MROWS * CEMB];                 // x as half [M][K]
__device__ __half g_qh [(size_t)BATCH * NHEAD * TSEQ * HSIZE]; // [B,H,T,D], q pre-scaled
__device__ __half g_kh [(size_t)BATCH * NHEAD * TSEQ * HSIZE]; // [B,H,T,D]
__device__ __half g_vh [(size_t)BATCH * NHEAD * TSEQ * HSIZE]; // [B,H,D,T] (transposed)
__device__ __half g_ah [(size_t)MROWS * CEMB];                 // attn out half [M][C]
__device__ __half g_wtq[(size_t)3 * CEMB * CEMB];              // [3C][C] K-major half
__device__ __half g_wtp[(size_t)CEMB * CEMB];                  // [C][C]  K-major half

// ---------------------------------------------------------------------------
// fp16 mma m16n8k16, fp32 accumulate
// ---------------------------------------------------------------------------
__device__ __forceinline__ void mma_f16(float& c0, float& c1, float& c2, float& c3,
                                        uint32_t a0, uint32_t a1, uint32_t a2, uint32_t a3,
                                        uint32_t b0, uint32_t b1) {
    asm volatile("mma.sync.aligned.m16n8k16.row.col.f32.f16.f16.f32 "
                 "{%0,%1,%2,%3}, {%4,%5,%6,%7}, {%8,%9}, {%0,%1,%2,%3};"
                 : "+f"(c0), "+f"(c1), "+f"(c2), "+f"(c3)
                 : "r"(a0), "r"(a1), "r"(a2), "r"(a3), "r"(b0), "r"(b1));
}
__device__ __forceinline__ uint32_t h2u(__half2 h) { return *(uint32_t*)&h; }

// ---------------------------------------------------------------------------
// x -> half
// ---------------------------------------------------------------------------
__global__ __launch_bounds__(256) void cvt_x(const float* __restrict__ in,
                                             __half* __restrict__ out)
{
    size_t i = ((size_t)blockIdx.x * 256 + threadIdx.x) * 8;
    float4 v0 = *(const float4*)(in + i);
    float4 v1 = *(const float4*)(in + i + 4);
    __half2 h0 = __floats2half2_rn(v0.x, v0.y);
    __half2 h1 = __floats2half2_rn(v0.z, v0.w);
    __half2 h2 = __floats2half2_rn(v1.x, v1.y);
    __half2 h3 = __floats2half2_rn(v1.z, v1.w);
    uint4 u = {h2u(h0), h2u(h1), h2u(h2), h2u(h3)};
    *(uint4*)(out + i) = u;
}

// ---------------------------------------------------------------------------
// Weight transpose fp32 [R][C] -> half [C][R]
// ---------------------------------------------------------------------------
__global__ __launch_bounds__(256) void transpose_h(const float* __restrict__ in,
                                                   __half* __restrict__ out, int R, int C)
{
    __shared__ float t[32][33];
    int bx = blockIdx.x * 32, by = blockIdx.y * 32;
#pragma unroll
    for (int i = 0; i < 32; i += 8)
        t[threadIdx.y + i][threadIdx.x] = in[(size_t)(by + threadIdx.y + i) * C + bx + threadIdx.x];
    __syncthreads();
#pragma unroll
    for (int i = 0; i < 32; i += 8)
        out[(size_t)(bx + threadIdx.y + i) * R + by + threadIdx.x] =
            __float2half_rn(t[threadIdx.x][threadIdx.y + i]);
}

// ---------------------------------------------------------------------------
// fp16 GEMM via mma.sync m16n8k16. C[M,N] = A[M,K]*Bt[N,K]^T (+bias).
// Tile 128(M)x256(N), 8 warps (4m x 2n), warp 32x128.
// K chunks of 64 halfs (128B rows), double-buffered, SW-xor swizzle on 16B segs.
// Per stage: A 128x64h (16KB) + B 256x64h (32KB). Dyn smem = 98304 B.
// mode 0: scatter g_qh(x0.125)/g_kh [B,H,T,D]; g_vh [B,H,D,T]. mode 1: C=acc+bias (f32).
// ---------------------------------------------------------------------------
#define GA_H   (128 * 64)            // halfs per A stage
#define GB_H   (256 * 64)
#define GST_H  (GA_H + GB_H)         // 24576 halfs per stage
__global__ __launch_bounds__(256) void gemm_h(
    const __half* __restrict__ A, const __half* __restrict__ Bt,
    const float* __restrict__ bias, float* __restrict__ C,
    int M, int N, int K, int mode)
{
    extern __shared__ __align__(16) __half hsm[];

    const int tid  = threadIdx.x;
    const int wid  = tid >> 5;
    const int lane = tid & 31;
    const int g    = lane >> 2;
    const int t    = lane & 3;
    const int wm   = wid & 3;
    const int wn   = wid >> 2;
    const int m0 = blockIdx.y * 128;
    const int n0 = blockIdx.x * 256;

    // loader: f = tid + i*256 ; row = f>>3, seg = f&7 (16B = 8 halfs)
    const int lrA = tid >> 3;
    const int lsA = tid & 7;

    float c[2][16][4];
#pragma unroll
    for (int mt = 0; mt < 2; ++mt)
#pragma unroll
        for (int nt = 0; nt < 16; ++nt)
#pragma unroll
            for (int j = 0; j < 4; ++j) c[mt][nt][j] = 0.f;

    uint4 pa[4], pb[8];
#pragma unroll
    for (int i = 0; i < 4; ++i)
        pa[i] = *(const uint4*)(A + (size_t)(m0 + lrA + i * 32) * K + lsA * 8);
#pragma unroll
    for (int i = 0; i < 8; ++i)
        pb[i] = *(const uint4*)(Bt + (size_t)(n0 + lrA + i * 32) * K + lsA * 8);
#pragma unroll
    for (int i = 0; i < 4; ++i) {
        int r = lrA + i * 32;
        *(uint4*)&hsm[r * 64 + ((lsA ^ (r & 7)) * 8)] = pa[i];
    }
#pragma unroll
    for (int i = 0; i < 8; ++i) {
        int r = lrA + i * 32;
        *(uint4*)&hsm[GA_H + r * 64 + ((lsA ^ (r & 7)) * 8)] = pb[i];
    }
    __syncthreads();

    const int KS = K >> 6;
#pragma unroll 1
    for (int s = 0; s < KS; ++s) {
        const __half* As = hsm + (s & 1) * GST_H;
        const __half* Bs = As + GA_H;

        if (s + 1 < KS) {
            const int k1 = ((s + 1) << 6) + lsA * 8;
#pragma unroll
            for (int i = 0; i < 4; ++i)
                pa[i] = *(const uint4*)(A + (size_t)(m0 + lrA + i * 32) * K + k1);
#pragma unroll
            for (int i = 0; i < 8; ++i)
                pb[i] = *(const uint4*)(Bt + (size_t)(n0 + lrA + i * 32) * K + k1);
        }

#pragma unroll
        for (int kt = 0; kt < 4; ++kt) {
            uint32_t bf[16][2];
#pragma unroll
            for (int nt = 0; nt < 16; ++nt) {
                int n = wn * 128 + nt * 8 + g;
                bf[nt][0] = *(const uint32_t*)&Bs[n * 64 + (((2 * kt) ^ g) * 8) + 2 * t];
                bf[nt][1] = *(const uint32_t*)&Bs[n * 64 + (((2 * kt + 1) ^ g) * 8) + 2 * t];
            }
#pragma unroll
            for (int mt = 0; mt < 2; ++mt) {
                int mb = wm * 32 + mt * 16;
                uint32_t a0 = *(const uint32_t*)&As[(mb + g) * 64 + (((2 * kt) ^ g) * 8) + 2 * t];
                uint32_t a1 = *(const uint32_t*)&As[(mb + g + 8) * 64 + (((2 * kt) ^ g) * 8) + 2 * t];
                uint32_t a2 = *(const uint32_t*)&As[(mb + g) * 64 + (((2 * kt + 1) ^ g) * 8) + 2 * t];
                uint32_t a3 = *(const uint32_t*)&As[(mb + g + 8) * 64 + (((2 * kt + 1) ^ g) * 8) + 2 * t];
#pragma unroll
                for (int nt = 0; nt < 16; ++nt)
                    mma_f16(c[mt][nt][0], c[mt][nt][1], c[mt][nt][2], c[mt][nt][3],
                            a0, a1, a2, a3, bf[nt][0], bf[nt][1]);
            }
        }

        if (s + 1 < KS) {
            __half* Ad = hsm + ((s + 1) & 1) * GST_H;
            __half* Bd = Ad + GA_H;
#pragma unroll
            for (int i = 0; i < 4; ++i) {
                int r = lrA + i * 32;
                *(uint4*)&Ad[r * 64 + ((lsA ^ (r & 7)) * 8)] = pa[i];
            }
#pragma unroll
            for (int i = 0; i < 8; ++i) {
                int r = lrA + i * 32;
                *(uint4*)&Bd[r * 64 + ((lsA ^ (r & 7)) * 8)] = pb[i];
            }
        }
        __syncthreads();
    }

    const int nwarp = n0 + wn * 128;
    if (mode == 0) {
#pragma unroll
        for (int mt = 0; mt < 2; ++mt) {
            int r0 = m0 + wm * 32 + mt * 16 + g;
            int bb0 = r0 >> 11, tt0 = r0 & (TSEQ - 1);
            int r1 = r0 + 8;
            int bb1 = r1 >> 11, tt1 = r1 & (TSEQ - 1);
#pragma unroll
            for (int nt = 0; nt < 16; ++nt) {
                int n = nwarp + nt * 8;
                int which = n >> 10;
                int h = (n & 1023) >> 6;
                int d = (n & 63) + 2 * t;
                if (which == 2) {
                    __half* base0 = g_vh + ((size_t)(bb0 * NHEAD + h)) * HSIZE * TSEQ;
                    __half* base1 = g_vh + ((size_t)(bb1 * NHEAD + h)) * HSIZE * TSEQ;
                    base0[(size_t)d * TSEQ + tt0]       = __float2half_rn(c[mt][nt][0]);
                    base0[(size_t)(d + 1) * TSEQ + tt0] = __float2half_rn(c[mt][nt][1]);
                    base1[(size_t)d * TSEQ + tt1]       = __float2half_rn(c[mt][nt][2]);
                    base1[(size_t)(d + 1) * TSEQ + tt1] = __float2half_rn(c[mt][nt][3]);
                } else {
                    const float sc = (which == 0) ? 0.125f : 1.0f;
                    __half* base = (which == 0) ? g_qh : g_kh;
                    __half* d0 = base + (((size_t)(bb0 * NHEAD + h) * TSEQ) + tt0) * HSIZE + d;
                    __half* d1 = base + (((size_t)(bb1 * NHEAD + h) * TSEQ) + tt1) * HSIZE + d;
                    *(__half2*)d0 = __floats2half2_rn(c[mt][nt][0] * sc, c[mt][nt][1] * sc);
                    *(__half2*)d1 = __floats2half2_rn(c[mt][nt][2] * sc, c[mt][nt][3] * sc);
                }
            }
        }
    } else {
#pragma unroll
        for (int mt = 0; mt < 2; ++mt) {
            int r0 = m0 + wm * 32 + mt * 16 + g;
#pragma unroll
            for (int nt = 0; nt < 16; ++nt) {
                int n = nwarp + nt * 8 + 2 * t;
                float2 bv = *(const float2*)(bias + n);
                float2 v0 = {c[mt][nt][0] + bv.x, c[mt][nt][1] + bv.y};
                float2 v1 = {c[mt][nt][2] + bv.x, c[mt][nt][3] + bv.y};
                *(float2*)(C + (size_t)r0 * N + n) = v0;
                *(float2*)(C + (size_t)(r0 + 8) * N + n) = v1;
            }
        }
    }
}

// ---------------------------------------------------------------------------
// fp16 causal flash attention (mma m16n8k16), 128-key tiles.
// CTA: 128 queries of one (b,h), 8 warps x 16 rows (warp-local softmax fp32).
// Smem (halfs): QP [128][128] (Q stage cols 0..63, then P), Ks [128][64],
// Vs [64][128]; all SW-xor swizzled on 16B segs. Dyn smem = 65536 B.
// ---------------------------------------------------------------------------
#define AQP_H (128 * 128)
#define AK_H  (128 * 64)
__global__ __launch_bounds__(256) void attn_h()
{
    extern __shared__ __align__(16) __half asm_[];
    __half* Qs = asm_;                 // Q: row stride 64 halfs (aliased by Ps)
    __half* Ks = asm_ + AQP_H;         // [128 keys][64 dim]
    __half* Vs = Ks + AK_H;            // [64 dim][128 keys]
    __half* Ps = Qs;                   // P: row stride 128 halfs

    const int tid  = threadIdx.x;
    const int wid  = tid >> 5;
    const int lane = tid & 31;
    const int g    = lane >> 2;
    const int t    = lane & 3;
    const int mb   = wid * 16;
    const int bh   = blockIdx.y;
    const int qb   = gridDim.x - 1 - blockIdx.x;   // heavy CTAs first
    const int q0   = qb * 128;

    // stage Q tile [128][64] halfs
    const __half* Qg = g_qh + ((size_t)bh * TSEQ + q0) * HSIZE;
#pragma unroll
    for (int i = 0; i < 4; ++i) {
        int f = tid + i * 256;
        int r = f >> 3, s = f & 7;
        *(uint4*)&Qs[r * 64 + ((s ^ (r & 7)) * 8)] =
            *(const uint4*)(Qg + (size_t)r * HSIZE + s * 8);
    }
    __syncthreads();

    // Q fragments (4 k16-chunks over 64 dims)
    uint32_t qa[4][4];
#pragma unroll
    for (int kb = 0; kb < 4; ++kb) {
        qa[kb][0] = *(const uint32_t*)&Qs[(mb + g) * 64 + (((2 * kb) ^ g) * 8) + 2 * t];
        qa[kb][1] = *(const uint32_t*)&Qs[(mb + g + 8) * 64 + (((2 * kb) ^ g) * 8) + 2 * t];
        qa[kb][2] = *(const uint32_t*)&Qs[(mb + g) * 64 + (((2 * kb + 1) ^ g) * 8) + 2 * t];
        qa[kb][3] = *(const uint32_t*)&Qs[(mb + g + 8) * 64 + (((2 * kb + 1) ^ g) * 8) + 2 * t];
    }
    __syncthreads();   // Qs free for P reuse

    float o[8][4];
#pragma unroll
    for (int nt = 0; nt < 8; ++nt)
#pragma unroll
        for (int j = 0; j < 4; ++j) o[nt][j] = 0.f;
    float m0 = -INFINITY, m1 = -INFINITY, l0 = 0.f, l1 = 0.f;

    const int row0 = q0 + mb + g;
    const int row1 = row0 + 8;

    const __half* Kg = g_kh + (size_t)bh * TSEQ * HSIZE;
    const __half* Vg = g_vh + (size_t)bh * HSIZE * TSEQ;

    for (int jt = 0; jt <= qb; ++jt) {
        // load K tile [128][64] and V tile [64][128]
#pragma unroll
        for (int i = 0; i < 4; ++i) {
            int f = tid + i * 256;
            int kr = f >> 3, ks = f & 7;
            *(uint4*)&Ks[kr * 64 + ((ks ^ (kr & 7)) * 8)] =
                *(const uint4*)(Kg + (size_t)(jt * 128 + kr) * HSIZE + ks * 8);
            int vr2 = f >> 4, vs = f & 15;
            *(uint4*)&Vs[vr2 * 128 + ((vs ^ (vr2 & 7)) * 8)] =
                *(const uint4*)(Vg + (size_t)vr2 * TSEQ + jt * 128 + vs * 8);
        }
        __syncthreads();

        // S = Q K^T : 16 rows x 128 keys per warp (4 kb x 16 nt mmas)
        float s[16][4];
#pragma unroll
        for (int nt = 0; nt < 16; ++nt)
#pragma unroll
            for (int j = 0; j < 4; ++j) s[nt][j] = 0.f;
#pragma unroll
        for (int kb = 0; kb < 4; ++kb) {
#pragma unroll
            for (int nt = 0; nt < 16; ++nt) {
                int n = nt * 8 + g;
                uint32_t b0 = *(const uint32_t*)&Ks[n * 64 + (((2 * kb) ^ g) * 8) + 2 * t];
                uint32_t b1 = *(const uint32_t*)&Ks[n * 64 + (((2 * kb + 1) ^ g) * 8) + 2 * t];
                mma_f16(s[nt][0], s[nt][1], s[nt][2], s[nt][3],
                        qa[kb][0], qa[kb][1], qa[kb][2], qa[kb][3], b0, b1);
            }
        }

        // causal mask on diagonal tile
        if (jt == qb) {
#pragma unroll
            for (int nt = 0; nt < 16; ++nt) {
                int col = jt * 128 + nt * 8 + 2 * t;
                if (col > row0)     s[nt][0] = -INFINITY;
                if (col + 1 > row0) s[nt][1] = -INFINITY;
                if (col > row1)     s[nt][2] = -INFINITY;
                if (col + 1 > row1) s[nt][3] = -INFINITY;
            }
        }

        // online softmax (fp32)
        float mx0 = -INFINITY, mx1 = -INFINITY;
#pragma unroll
        for (int nt = 0; nt < 16; ++nt) {
            mx0 = fmaxf(mx0, fmaxf(s[nt][0], s[nt][1]));
            mx1 = fmaxf(mx1, fmaxf(s[nt][2], s[nt][3]));
        }
        mx0 = fmaxf(mx0, __shfl_xor_sync(0xffffffffu, mx0, 1));
        mx0 = fmaxf(mx0, __shfl_xor_sync(0xffffffffu, mx0, 2));
        mx1 = fmaxf(mx1, __shfl_xor_sync(0xffffffffu, mx1, 1));
        mx1 = fmaxf(mx1, __shfl_xor_sync(0xffffffffu, mx1, 2));
        float nm0 = fmaxf(m0, mx0), nm1 = fmaxf(m1, mx1);
        float cr0 = __expf(m0 - nm0), cr1 = __expf(m1 - nm1);
        l0 *= cr0; l1 *= cr1;
#pragma unroll
        for (int nt = 0; nt < 8; ++nt) {
            o[nt][0] *= cr0; o[nt][1] *= cr0;
            o[nt][2] *= cr1; o[nt][3] *= cr1;
        }
        float s0 = 0.f, s1 = 0.f;
#pragma unroll
        for (int nt = 0; nt < 16; ++nt) {
            float p00 = __expf(s[nt][0] - nm0);
            float p01 = __expf(s[nt][1] - nm0);
            float p10 = __expf(s[nt][2] - nm1);
            float p11 = __expf(s[nt][3] - nm1);
            s0 += p00 + p01; s1 += p10 + p11;
            // P store: col 8nt+2t, seg = nt, swizzled by row&7 = g
            *(__half2*)&Ps[(mb + g) * 128 + ((nt ^ g) * 8) + 2 * t] =
                __floats2half2_rn(p00, p01);
            *(__half2*)&Ps[(mb + g + 8) * 128 + ((nt ^ g) * 8) + 2 * t] =
                __floats2half2_rn(p10, p11);
        }
        s0 += __shfl_xor_sync(0xffffffffu, s0, 1);
        s0 += __shfl_xor_sync(0xffffffffu, s0, 2);
        s1 += __shfl_xor_sync(0xffffffffu, s1, 1);
        s1 += __shfl_xor_sync(0xffffffffu, s1, 2);
        l0 += s0; l1 += s1;
        m0 = nm0; m1 = nm1;
        __syncwarp();

        // O += P V : 8 kb (128 keys / k16) x 8 nt (64 dims)
#pragma unroll
        for (int kb = 0; kb < 8; ++kb) {
            uint32_t pa0 = *(const uint32_t*)&Ps[(mb + g) * 128 + (((2 * kb) ^ g) * 8) + 2 * t];
            uint32_t pa1 = *(const uint32_t*)&Ps[(mb + g + 8) * 128 + (((2 * kb) ^ g) * 8) + 2 * t];
            uint32_t pa2 = *(const uint32_t*)&Ps[(mb + g) * 128 + (((2 * kb + 1) ^ g) * 8) + 2 * t];
            uint32_t pa3 = *(const uint32_t*)&Ps[(mb + g + 8) * 128 + (((2 * kb + 1) ^ g) * 8) + 2 * t];
#pragma unroll
            for (int nt = 0; nt < 8; ++nt) {
                int n = nt * 8 + g;
                uint32_t b0 = *(const uint32_t*)&Vs[n * 128 + (((2 * kb) ^ g) * 8) + 2 * t];
                uint32_t b1 = *(const uint32_t*)&Vs[n * 128 + (((2 * kb + 1) ^ g) * 8) + 2 * t];
                mma_f16(o[nt][0], o[nt][1], o[nt][2], o[nt][3],
                        pa0, pa1, pa2, pa3, b0, b1);
            }
        }
        __syncthreads();   // protect Ks/Vs/Ps before next tile
    }

    // write O -> g_ah [M][C] half
    const int b = bh >> 4, h = bh & 15;
    const float inv0 = 1.f / l0, inv1 = 1.f / l1;
    __half* O0 = g_ah + ((size_t)(b * TSEQ) + row0) * CEMB + h * HSIZE;
    __half* O1 = g_ah + ((size_t)(b * TSEQ) + row1) * CEMB + h * HSIZE;
#pragma unroll
    for (int nt = 0; nt < 8; ++nt) {
        int d = nt * 8 + 2 * t;
        *(__half2*)(O0 + d) = __floats2half2_rn(o[nt][0] * inv0, o[nt][1] * inv0);
        *(__half2*)(O1 + d) = __floats2half2_rn(o[nt][2] * inv1, o[nt][3] * inv1);
    }
}

// ---------------------------------------------------------------------------
extern "C" void kernel_launch(void* const* d_in, const int* in_sizes, int n_in,
                              void* d_out, int out_size)
{
    const float* x      = (const float*)d_in[0];
    const float* w_qkv  = (const float*)d_in[1];
    const float* w_proj = (const float*)d_in[2];
    const float* b_proj = (const float*)d_in[3];
    float* out = (float*)d_out;

    __half *xh = nullptr, *ah = nullptr, *wtq = nullptr, *wtp = nullptr;
    cudaGetSymbolAddress((void**)&xh,  g_xh);
    cudaGetSymbolAddress((void**)&ah,  g_ah);
    cudaGetSymbolAddress((void**)&wtq, g_wtq);
    cudaGetSymbolAddress((void**)&wtp, g_wtp);

    const int ATTN_SMEM = (AQP_H + AK_H + 64 * 128) * 2;   // 65536
    const int GEMM_SMEM = 2 * GST_H * 2;                   // 98304
    cudaFuncSetAttribute(attn_h, cudaFuncAttributeMaxDynamicSharedMemorySize, ATTN_SMEM);
    cudaFuncSetAttribute(gemm_h, cudaFuncAttributeMaxDynamicSharedMemorySize, GEMM_SMEM);

    // 0) convert x, transpose weights (K-major, half)
    cvt_x<<<MROWS * CEMB / (256 * 8), 256>>>(x, xh);
    transpose_h<<<dim3(3 * CEMB / 32, CEMB / 32), dim3(32, 8)>>>(w_qkv, wtq, CEMB, 3 * CEMB);
    transpose_h<<<dim3(CEMB / 32, CEMB / 32), dim3(32, 8)>>>(w_proj, wtp, CEMB, CEMB);

    // 1) QKV GEMM (fp16 mma) + head-major scatter (V transposed)
    gemm_h<<<dim3(3 * CEMB / 256, MROWS / 128), 256, GEMM_SMEM>>>(
        xh, wtq, nullptr, nullptr, MROWS, 3 * CEMB, CEMB, 0);

    // 2) Causal flash attention (fp16 mma)
    attn_h<<<dim3(TSEQ / 128, BATCH * NHEAD), 256, ATTN_SMEM>>>();

    // 3) Output projection + bias (fp16 mma, fp32 out)
    gemm_h<<<dim3(CEMB / 256, MROWS / 128), 256, GEMM_SMEM>>>(
        ah, wtp, b_proj, out, MROWS, CEMB, CEMB, 1);
}

// round 10
// speedup vs baseline: 2.1366x; 1.0853x over previous
#include <cuda_runtime.h>
#include <cuda_fp16.h>
#include <math.h>
#include <stdint.h>

// Problem constants
#define BATCH   4
#define TSEQ    2048
#define NHEAD   16
#define HSIZE   64
#define CEMB    1024
#define MROWS   (BATCH*TSEQ)   // 8192

// Scratch (device globals; fp16 operands, fp32 accum everywhere)
__device__ __half g_xh [(size_t)MROWS * CEMB];
__device__ __half g_qh [(size_t)BATCH * NHEAD * TSEQ * HSIZE]; // [B,H,T,D], q pre-scaled
__device__ __half g_kh [(size_t)BATCH * NHEAD * TSEQ * HSIZE]; // [B,H,T,D]
__device__ __half g_vh [(size_t)BATCH * NHEAD * TSEQ * HSIZE]; // [B,H,D,T] (transposed)
__device__ __half g_ah [(size_t)MROWS * CEMB];
__device__ __half g_wtq[(size_t)3 * CEMB * CEMB];              // [3C][C] K-major
__device__ __half g_wtp[(size_t)CEMB * CEMB];                  // [C][C]  K-major

// ---------------------------------------------------------------------------
// helpers
// ---------------------------------------------------------------------------
__device__ __forceinline__ void mma_f16(float& c0, float& c1, float& c2, float& c3,
                                        uint32_t a0, uint32_t a1, uint32_t a2, uint32_t a3,
                                        uint32_t b0, uint32_t b1) {
    asm volatile("mma.sync.aligned.m16n8k16.row.col.f32.f16.f16.f32 "
                 "{%0,%1,%2,%3}, {%4,%5,%6,%7}, {%8,%9}, {%0,%1,%2,%3};"
                 : "+f"(c0), "+f"(c1), "+f"(c2), "+f"(c3)
                 : "r"(a0), "r"(a1), "r"(a2), "r"(a3), "r"(b0), "r"(b1));
}
__device__ __forceinline__ uint32_t h2u(__half2 h) { return *(uint32_t*)&h; }
__device__ __forceinline__ uint32_t smem_u32(const void* p) {
    uint32_t a;
    asm("{ .reg .u64 t; cvta.to.shared.u64 t, %1; cvt.u32.u64 %0, t; }" : "=r"(a) : "l"(p));
    return a;
}
#define CP_ASYNC16(dst, src) \
    asm volatile("cp.async.cg.shared.global [%0], [%1], 16;" :: "r"(dst), "l"(src))
#define CP_COMMIT()  asm volatile("cp.async.commit_group;" ::)
#define CP_WAIT(n)   asm volatile("cp.async.wait_group %0;" :: "n"(n))

// ---------------------------------------------------------------------------
// x -> half
// ---------------------------------------------------------------------------
__global__ __launch_bounds__(256) void cvt_x(const float* __restrict__ in,
                                             __half* __restrict__ out)
{
    size_t i = ((size_t)blockIdx.x * 256 + threadIdx.x) * 8;
    float4 v0 = *(const float4*)(in + i);
    float4 v1 = *(const float4*)(in + i + 4);
    uint4 u = {h2u(__floats2half2_rn(v0.x, v0.y)), h2u(__floats2half2_rn(v0.z, v0.w)),
               h2u(__floats2half2_rn(v1.x, v1.y)), h2u(__floats2half2_rn(v1.z, v1.w))};
    *(uint4*)(out + i) = u;
}

// ---------------------------------------------------------------------------
// Weight transpose fp32 [R][C] -> half [C][R]
// ---------------------------------------------------------------------------
__global__ __launch_bounds__(256) void transpose_h(const float* __restrict__ in,
                                                   __half* __restrict__ out, int R, int C)
{
    __shared__ float t[32][33];
    int bx = blockIdx.x * 32, by = blockIdx.y * 32;
#pragma unroll
    for (int i = 0; i < 32; i += 8)
        t[threadIdx.y + i][threadIdx.x] = in[(size_t)(by + threadIdx.y + i) * C + bx + threadIdx.x];
    __syncthreads();
#pragma unroll
    for (int i = 0; i < 32; i += 8)
        out[(size_t)(bx + threadIdx.y + i) * R + by + threadIdx.x] =
            __float2half_rn(t[threadIdx.x][threadIdx.y + i]);
}

// ---------------------------------------------------------------------------
// fp16 GEMM, mma m16n8k16, cp.async 3-stage pipeline.
// Tile 128(M)x256(N), 8 warps (4m x 2n), warp 32x128. K chunks of 64 halfs.
// Per stage: A 128x64h + B 256x64h = 48KB. Dyn smem = 147456 B.
// ---------------------------------------------------------------------------
#define GA_H   (128 * 64)
#define GB_H   (256 * 64)
#define GST_H  (GA_H + GB_H)
#define GSTAGES 3
__global__ __launch_bounds__(256) void gemm_h(
    const __half* __restrict__ A, const __half* __restrict__ Bt,
    const float* __restrict__ bias, float* __restrict__ C,
    int M, int N, int K, int mode)
{
    extern __shared__ __align__(16) __half hsm[];
    const uint32_t sb = smem_u32(hsm);

    const int tid  = threadIdx.x;
    const int wid  = tid >> 5;
    const int lane = tid & 31;
    const int g    = lane >> 2;
    const int t    = lane & 3;
    const int wm   = wid & 3;
    const int wn   = wid >> 2;
    const int m0 = blockIdx.y * 128;
    const int n0 = blockIdx.x * 256;

    const int lrA = tid >> 3;
    const int lsA = tid & 7;

    float c[2][16][4];
#pragma unroll
    for (int mt = 0; mt < 2; ++mt)
#pragma unroll
        for (int nt = 0; nt < 16; ++nt)
#pragma unroll
            for (int j = 0; j < 4; ++j) c[mt][nt][j] = 0.f;

    auto issue = [&](int s) {
        const int base = (s % GSTAGES) * GST_H;
        const int koff = (s << 6) + lsA * 8;
#pragma unroll
        for (int i = 0; i < 4; ++i) {
            int r = lrA + i * 32;
            uint32_t dst = sb + (uint32_t)(base + r * 64 + ((lsA ^ (r & 7)) * 8)) * 2;
            CP_ASYNC16(dst, A + (size_t)(m0 + r) * K + koff);
        }
#pragma unroll
        for (int i = 0; i < 8; ++i) {
            int r = lrA + i * 32;
            uint32_t dst = sb + (uint32_t)(base + GA_H + r * 64 + ((lsA ^ (r & 7)) * 8)) * 2;
            CP_ASYNC16(dst, Bt + (size_t)(n0 + r) * K + koff);
        }
        CP_COMMIT();
    };

    const int KS = K >> 6;
    issue(0);
    issue(1);

#pragma unroll 1
    for (int s = 0; s < KS; ++s) {
        if (s + 1 < KS) { CP_WAIT(1); } else { CP_WAIT(0); }
        __syncthreads();
        if (s + 2 < KS) issue(s + 2);

        const __half* As = hsm + (s % GSTAGES) * GST_H;
        const __half* Bs = As + GA_H;

#pragma unroll
        for (int kt = 0; kt < 4; ++kt) {
            uint32_t bf[16][2];
#pragma unroll
            for (int nt = 0; nt < 16; ++nt) {
                int n = wn * 128 + nt * 8 + g;
                bf[nt][0] = *(const uint32_t*)&Bs[n * 64 + (((2 * kt) ^ g) * 8) + 2 * t];
                bf[nt][1] = *(const uint32_t*)&Bs[n * 64 + (((2 * kt + 1) ^ g) * 8) + 2 * t];
            }
#pragma unroll
            for (int mt = 0; mt < 2; ++mt) {
                int mb = wm * 32 + mt * 16;
                uint32_t a0 = *(const uint32_t*)&As[(mb + g) * 64 + (((2 * kt) ^ g) * 8) + 2 * t];
                uint32_t a1 = *(const uint32_t*)&As[(mb + g + 8) * 64 + (((2 * kt) ^ g) * 8) + 2 * t];
                uint32_t a2 = *(const uint32_t*)&As[(mb + g) * 64 + (((2 * kt + 1) ^ g) * 8) + 2 * t];
                uint32_t a3 = *(const uint32_t*)&As[(mb + g + 8) * 64 + (((2 * kt + 1) ^ g) * 8) + 2 * t];
#pragma unroll
                for (int nt = 0; nt < 16; ++nt)
                    mma_f16(c[mt][nt][0], c[mt][nt][1], c[mt][nt][2], c[mt][nt][3],
                            a0, a1, a2, a3, bf[nt][0], bf[nt][1]);
            }
        }
    }

    const int nwarp = n0 + wn * 128;
    if (mode == 0) {
#pragma unroll
        for (int mt = 0; mt < 2; ++mt) {
            int r0 = m0 + wm * 32 + mt * 16 + g;
            int bb0 = r0 >> 11, tt0 = r0 & (TSEQ - 1);
            int r1 = r0 + 8;
            int bb1 = r1 >> 11, tt1 = r1 & (TSEQ - 1);
#pragma unroll
            for (int nt = 0; nt < 16; ++nt) {
                int n = nwarp + nt * 8;
                int which = n >> 10;
                int h = (n & 1023) >> 6;
                int d = (n & 63) + 2 * t;
                if (which == 2) {
                    __half* base0 = g_vh + ((size_t)(bb0 * NHEAD + h)) * HSIZE * TSEQ;
                    __half* base1 = g_vh + ((size_t)(bb1 * NHEAD + h)) * HSIZE * TSEQ;
                    base0[(size_t)d * TSEQ + tt0]       = __float2half_rn(c[mt][nt][0]);
                    base0[(size_t)(d + 1) * TSEQ + tt0] = __float2half_rn(c[mt][nt][1]);
                    base1[(size_t)d * TSEQ + tt1]       = __float2half_rn(c[mt][nt][2]);
                    base1[(size_t)(d + 1) * TSEQ + tt1] = __float2half_rn(c[mt][nt][3]);
                } else {
                    const float sc = (which == 0) ? 0.125f : 1.0f;
                    __half* base = (which == 0) ? g_qh : g_kh;
                    __half* d0 = base + (((size_t)(bb0 * NHEAD + h) * TSEQ) + tt0) * HSIZE + d;
                    __half* d1 = base + (((size_t)(bb1 * NHEAD + h) * TSEQ) + tt1) * HSIZE + d;
                    *(__half2*)d0 = __floats2half2_rn(c[mt][nt][0] * sc, c[mt][nt][1] * sc);
                    *(__half2*)d1 = __floats2half2_rn(c[mt][nt][2] * sc, c[mt][nt][3] * sc);
                }
            }
        }
    } else {
#pragma unroll
        for (int mt = 0; mt < 2; ++mt) {
            int r0 = m0 + wm * 32 + mt * 16 + g;
#pragma unroll
            for (int nt = 0; nt < 16; ++nt) {
                int n = nwarp + nt * 8 + 2 * t;
                float2 bv = *(const float2*)(bias + n);
                float2 v0 = {c[mt][nt][0] + bv.x, c[mt][nt][1] + bv.y};
                float2 v1 = {c[mt][nt][2] + bv.x, c[mt][nt][3] + bv.y};
                *(float2*)(C + (size_t)r0 * N + n) = v0;
                *(float2*)(C + (size_t)(r0 + 8) * N + n) = v1;
            }
        }
    }
}

// ---------------------------------------------------------------------------
// fp16 causal flash attention, cp.async double-buffered KV, 128-key tiles.
// Smem (halfs): QP [128][128] (Q stage cols 0..63 then P), 2 x {K 128x64, V 64x128}.
// One __syncthreads per tile. Dyn smem = 98304 B.
// ---------------------------------------------------------------------------
#define AQP_H (128 * 128)
#define AK_H  (128 * 64)
#define KV_H  (AK_H + 64 * 128)   // 16384 halfs per buffer
__global__ __launch_bounds__(256) void attn_h()
{
    extern __shared__ __align__(16) __half asm_[];
    __half* Qs = asm_;
    __half* Ps = Qs;
    const uint32_t sb = smem_u32(asm_);

    const int tid  = threadIdx.x;
    const int wid  = tid >> 5;
    const int lane = tid & 31;
    const int g    = lane >> 2;
    const int t    = lane & 3;
    const int mb   = wid * 16;
    const int bh   = blockIdx.y;
    const int qb   = gridDim.x - 1 - blockIdx.x;   // heavy CTAs first
    const int q0   = qb * 128;

    const __half* Kg = g_kh + (size_t)bh * TSEQ * HSIZE;
    const __half* Vg = g_vh + (size_t)bh * HSIZE * TSEQ;

    auto issueKV = [&](int jt) {
        const int base = AQP_H + (jt & 1) * KV_H;
#pragma unroll
        for (int i = 0; i < 4; ++i) {
            int f = tid + i * 256;
            int kr = f >> 3, ks = f & 7;
            uint32_t dst = sb + (uint32_t)(base + kr * 64 + ((ks ^ (kr & 7)) * 8)) * 2;
            CP_ASYNC16(dst, Kg + (size_t)(jt * 128 + kr) * HSIZE + ks * 8);
        }
#pragma unroll
        for (int i = 0; i < 4; ++i) {
            int f = tid + i * 256;
            int vr = f >> 4, vs = f & 15;
            uint32_t dst = sb + (uint32_t)(base + AK_H + vr * 128 + ((vs ^ (vr & 7)) * 8)) * 2;
            CP_ASYNC16(dst, Vg + (size_t)vr * TSEQ + jt * 128 + vs * 8);
        }
        CP_COMMIT();
    };

    issueKV(0);

    // stage Q tile [128][64] halfs (regular loads, overlapped with KV copy)
    const __half* Qg = g_qh + ((size_t)bh * TSEQ + q0) * HSIZE;
#pragma unroll
    for (int i = 0; i < 4; ++i) {
        int f = tid + i * 256;
        int r = f >> 3, s = f & 7;
        *(uint4*)&Qs[r * 64 + ((s ^ (r & 7)) * 8)] =
            *(const uint4*)(Qg + (size_t)r * HSIZE + s * 8);
    }
    __syncthreads();

    uint32_t qa[4][4];
#pragma unroll
    for (int kb = 0; kb < 4; ++kb) {
        qa[kb][0] = *(const uint32_t*)&Qs[(mb + g) * 64 + (((2 * kb) ^ g) * 8) + 2 * t];
        qa[kb][1] = *(const uint32_t*)&Qs[(mb + g + 8) * 64 + (((2 * kb) ^ g) * 8) + 2 * t];
        qa[kb][2] = *(const uint32_t*)&Qs[(mb + g) * 64 + (((2 * kb + 1) ^ g) * 8) + 2 * t];
        qa[kb][3] = *(const uint32_t*)&Qs[(mb + g + 8) * 64 + (((2 * kb + 1) ^ g) * 8) + 2 * t];
    }

    float o[8][4];
#pragma unroll
    for (int nt = 0; nt < 8; ++nt)
#pragma unroll
        for (int j = 0; j < 4; ++j) o[nt][j] = 0.f;
    float m0 = -INFINITY, m1 = -INFINITY, l0 = 0.f, l1 = 0.f;

    const int row0 = q0 + mb + g;
    const int row1 = row0 + 8;

    for (int jt = 0; jt <= qb; ++jt) {
        CP_WAIT(0);
        __syncthreads();                 // KV(jt) ready; all warps done with jt-1
        if (jt < qb) issueKV(jt + 1);    // overlaps with compute below

        const __half* Ks = asm_ + AQP_H + (jt & 1) * KV_H;
        const __half* Vs = Ks + AK_H;

        // S = Q K^T
        float s[16][4];
#pragma unroll
        for (int nt = 0; nt < 16; ++nt)
#pragma unroll
            for (int j = 0; j < 4; ++j) s[nt][j] = 0.f;
#pragma unroll
        for (int kb = 0; kb < 4; ++kb) {
#pragma unroll
            for (int nt = 0; nt < 16; ++nt) {
                int n = nt * 8 + g;
                uint32_t b0 = *(const uint32_t*)&Ks[n * 64 + (((2 * kb) ^ g) * 8) + 2 * t];
                uint32_t b1 = *(const uint32_t*)&Ks[n * 64 + (((2 * kb + 1) ^ g) * 8) + 2 * t];
                mma_f16(s[nt][0], s[nt][1], s[nt][2], s[nt][3],
                        qa[kb][0], qa[kb][1], qa[kb][2], qa[kb][3], b0, b1);
            }
        }

        if (jt == qb) {
#pragma unroll
            for (int nt = 0; nt < 16; ++nt) {
                int col = jt * 128 + nt * 8 + 2 * t;
                if (col > row0)     s[nt][0] = -INFINITY;
                if (col + 1 > row0) s[nt][1] = -INFINITY;
                if (col > row1)     s[nt][2] = -INFINITY;
                if (col + 1 > row1) s[nt][3] = -INFINITY;
            }
        }

        // online softmax (fp32)
        float mx0 = -INFINITY, mx1 = -INFINITY;
#pragma unroll
        for (int nt = 0; nt < 16; ++nt) {
            mx0 = fmaxf(mx0, fmaxf(s[nt][0], s[nt][1]));
            mx1 = fmaxf(mx1, fmaxf(s[nt][2], s[nt][3]));
        }
        mx0 = fmaxf(mx0, __shfl_xor_sync(0xffffffffu, mx0, 1));
        mx0 = fmaxf(mx0, __shfl_xor_sync(0xffffffffu, mx0, 2));
        mx1 = fmaxf(mx1, __shfl_xor_sync(0xffffffffu, mx1, 1));
        mx1 = fmaxf(mx1, __shfl_xor_sync(0xffffffffu, mx1, 2));
        float nm0 = fmaxf(m0, mx0), nm1 = fmaxf(m1, mx1);
        float cr0 = __expf(m0 - nm0), cr1 = __expf(m1 - nm1);
        l0 *= cr0; l1 *= cr1;
#pragma unroll
        for (int nt = 0; nt < 8; ++nt) {
            o[nt][0] *= cr0; o[nt][1] *= cr0;
            o[nt][2] *= cr1; o[nt][3] *= cr1;
        }
        float s0 = 0.f, s1 = 0.f;
#pragma unroll
        for (int nt = 0; nt < 16; ++nt) {
            float p00 = __expf(s[nt][0] - nm0);
            float p01 = __expf(s[nt][1] - nm0);
            float p10 = __expf(s[nt][2] - nm1);
            float p11 = __expf(s[nt][3] - nm1);
            s0 += p00 + p01; s1 += p10 + p11;
            *(__half2*)&Ps[(mb + g) * 128 + ((nt ^ g) * 8) + 2 * t] =
                __floats2half2_rn(p00, p01);
            *(__half2*)&Ps[(mb + g + 8) * 128 + ((nt ^ g) * 8) + 2 * t] =
                __floats2half2_rn(p10, p11);
        }
        s0 += __shfl_xor_sync(0xffffffffu, s0, 1);
        s0 += __shfl_xor_sync(0xffffffffu, s0, 2);
        s1 += __shfl_xor_sync(0xffffffffu, s1, 1);
        s1 += __shfl_xor_sync(0xffffffffu, s1, 2);
        l0 += s0; l1 += s1;
        m0 = nm0; m1 = nm1;
        __syncwarp();

        // O += P V
#pragma unroll
        for (int kb = 0; kb < 8; ++kb) {
            uint32_t pa0 = *(const uint32_t*)&Ps[(mb + g) * 128 + (((2 * kb) ^ g) * 8) + 2 * t];
            uint32_t pa1 = *(const uint32_t*)&Ps[(mb + g + 8) * 128 + (((2 * kb) ^ g) * 8) + 2 * t];
            uint32_t pa2 = *(const uint32_t*)&Ps[(mb + g) * 128 + (((2 * kb + 1) ^ g) * 8) + 2 * t];
            uint32_t pa3 = *(const uint32_t*)&Ps[(mb + g + 8) * 128 + (((2 * kb + 1) ^ g) * 8) + 2 * t];
#pragma unroll
            for (int nt = 0; nt < 8; ++nt) {
                int n = nt * 8 + g;
                uint32_t b0 = *(const uint32_t*)&Vs[n * 128 + (((2 * kb) ^ g) * 8) + 2 * t];
                uint32_t b1 = *(const uint32_t*)&Vs[n * 128 + (((2 * kb + 1) ^ g) * 8) + 2 * t];
                mma_f16(o[nt][0], o[nt][1], o[nt][2], o[nt][3],
                        pa0, pa1, pa2, pa3, b0, b1);
            }
        }
    }

    const int b = bh >> 4, h = bh & 15;
    const float inv0 = 1.f / l0, inv1 = 1.f / l1;
    __half* O0 = g_ah + ((size_t)(b * TSEQ) + row0) * CEMB + h * HSIZE;
    __half* O1 = g_ah + ((size_t)(b * TSEQ) + row1) * CEMB + h * HSIZE;
#pragma unroll
    for (int nt = 0; nt < 8; ++nt) {
        int d = nt * 8 + 2 * t;
        *(__half2*)(O0 + d) = __floats2half2_rn(o[nt][0] * inv0, o[nt][1] * inv0);
        *(__half2*)(O1 + d) = __floats2half2_rn(o[nt][2] * inv1, o[nt][3] * inv1);
    }
}

// ---------------------------------------------------------------------------
extern "C" void kernel_launch(void* const* d_in, const int* in_sizes, int n_in,
                              void* d_out, int out_size)
{
    const float* x      = (const float*)d_in[0];
    const float* w_qkv  = (const float*)d_in[1];
    const float* w_proj = (const float*)d_in[2];
    const float* b_proj = (const float*)d_in[3];
    float* out = (float*)d_out;

    __half *xh = nullptr, *ah = nullptr, *wtq = nullptr, *wtp = nullptr;
    cudaGetSymbolAddress((void**)&xh,  g_xh);
    cudaGetSymbolAddress((void**)&ah,  g_ah);
    cudaGetSymbolAddress((void**)&wtq, g_wtq);
    cudaGetSymbolAddress((void**)&wtp, g_wtp);

    const int ATTN_SMEM = (AQP_H + 2 * KV_H) * 2;       // 98304
    const int GEMM_SMEM = GSTAGES * GST_H * 2;          // 147456
    cudaFuncSetAttribute(attn_h, cudaFuncAttributeMaxDynamicSharedMemorySize, ATTN_SMEM);
    cudaFuncSetAttribute(gemm_h, cudaFuncAttributeMaxDynamicSharedMemorySize, GEMM_SMEM);

    // 0) convert x, transpose weights (K-major, half)
    cvt_x<<<MROWS * CEMB / (256 * 8), 256>>>(x, xh);
    transpose_h<<<dim3(3 * CEMB / 32, CEMB / 32), dim3(32, 8)>>>(w_qkv, wtq, CEMB, 3 * CEMB);
    transpose_h<<<dim3(CEMB / 32, CEMB / 32), dim3(32, 8)>>>(w_proj, wtp, CEMB, CEMB);

    // 1) QKV GEMM (fp16 mma, cp.async) + head-major scatter (V transposed)
    gemm_h<<<dim3(3 * CEMB / 256, MROWS / 128), 256, GEMM_SMEM>>>(
        xh, wtq, nullptr, nullptr, MROWS, 3 * CEMB, CEMB, 0);

    // 2) Causal flash attention (fp16 mma, cp.async double-buffered KV)
    attn_h<<<dim3(TSEQ / 128, BATCH * NHEAD), 256, ATTN_SMEM>>>();

    // 3) Output projection + bias (fp16 mma, fp32 out)
    gemm_h<<<dim3(CEMB / 256, MROWS / 128), 256, GEMM_SMEM>>>(
        ah, wtp, b_proj, out, MROWS, CEMB, CEMB, 1);
}

// round 11
// speedup vs baseline: 2.3608x; 1.1049x over previous
#include <cuda_runtime.h>
#include <cuda_fp16.h>
#include <math.h>
#include <stdint.h>

// Problem constants
#define BATCH   4
#define TSEQ    2048
#define NHEAD   16
#define HSIZE   64
#define CEMB    1024
#define MROWS   (BATCH*TSEQ)   // 8192

// Scratch (device globals; fp16 operands, fp32 accum everywhere)
__device__ __half g_xh [(size_t)MROWS * CEMB];
__device__ __half g_qh [(size_t)BATCH * NHEAD * TSEQ * HSIZE]; // [B,H,T,D], q pre-scaled
__device__ __half g_kh [(size_t)BATCH * NHEAD * TSEQ * HSIZE]; // [B,H,T,D]
__device__ __half g_vh [(size_t)BATCH * NHEAD * TSEQ * HSIZE]; // [B,H,D,T] (transposed)
__device__ __half g_ah [(size_t)MROWS * CEMB];
__device__ __half g_wtq[(size_t)3 * CEMB * CEMB];              // [3C][C] K-major
__device__ __half g_wtp[(size_t)CEMB * CEMB];                  // [C][C]  K-major

// ---------------------------------------------------------------------------
// helpers
// ---------------------------------------------------------------------------
__device__ __forceinline__ void mma_f16(float& c0, float& c1, float& c2, float& c3,
                                        uint32_t a0, uint32_t a1, uint32_t a2, uint32_t a3,
                                        uint32_t b0, uint32_t b1) {
    asm volatile("mma.sync.aligned.m16n8k16.row.col.f32.f16.f16.f32 "
                 "{%0,%1,%2,%3}, {%4,%5,%6,%7}, {%8,%9}, {%0,%1,%2,%3};"
                 : "+f"(c0), "+f"(c1), "+f"(c2), "+f"(c3)
                 : "r"(a0), "r"(a1), "r"(a2), "r"(a3), "r"(b0), "r"(b1));
}
__device__ __forceinline__ uint32_t h2u(__half2 h) { return *(uint32_t*)&h; }
__device__ __forceinline__ uint32_t smem_u32(const void* p) {
    uint32_t a;
    asm("{ .reg .u64 t; cvta.to.shared.u64 t, %1; cvt.u32.u64 %0, t; }" : "=r"(a) : "l"(p));
    return a;
}
#define CP_ASYNC16(dst, src) \
    asm volatile("cp.async.cg.shared.global [%0], [%1], 16;" :: "r"(dst), "l"(src))
#define CP_COMMIT()  asm volatile("cp.async.commit_group;" ::)
#define CP_WAIT(n)   asm volatile("cp.async.wait_group %0;" :: "n"(n))

// ---------------------------------------------------------------------------
// x -> half
// ---------------------------------------------------------------------------
__global__ __launch_bounds__(256) void cvt_x(const float* __restrict__ in,
                                             __half* __restrict__ out)
{
    size_t i = ((size_t)blockIdx.x * 256 + threadIdx.x) * 8;
    float4 v0 = *(const float4*)(in + i);
    float4 v1 = *(const float4*)(in + i + 4);
    uint4 u = {h2u(__floats2half2_rn(v0.x, v0.y)), h2u(__floats2half2_rn(v0.z, v0.w)),
               h2u(__floats2half2_rn(v1.x, v1.y)), h2u(__floats2half2_rn(v1.z, v1.w))};
    *(uint4*)(out + i) = u;
}

// ---------------------------------------------------------------------------
// Weight transpose fp32 [R][C] -> half [C][R]
// ---------------------------------------------------------------------------
__global__ __launch_bounds__(256) void transpose_h(const float* __restrict__ in,
                                                   __half* __restrict__ out, int R, int C)
{
    __shared__ float t[32][33];
    int bx = blockIdx.x * 32, by = blockIdx.y * 32;
#pragma unroll
    for (int i = 0; i < 32; i += 8)
        t[threadIdx.y + i][threadIdx.x] = in[(size_t)(by + threadIdx.y + i) * C + bx + threadIdx.x];
    __syncthreads();
#pragma unroll
    for (int i = 0; i < 32; i += 8)
        out[(size_t)(bx + threadIdx.y + i) * R + by + threadIdx.x] =
            __float2half_rn(t[threadIdx.x][threadIdx.y + i]);
}

// ---------------------------------------------------------------------------
// fp16 GEMM, mma m16n8k16, cp.async 3-stage pipeline, 2 CTAs/SM.
// Tile 128(M)x128(N), 8 warps (4m x 2n), warp 32x64 = 2(m16) x 8(n8) mma tiles.
// K chunks of 64 halfs. Per stage: A 128x64h + B 128x64h = 32KB. Smem = 96KB.
// mode 0: scatter g_qh(x0.125)/g_kh [B,H,T,D]; g_vh [B,H,D,T]. mode 1: C=acc+bias.
// ---------------------------------------------------------------------------
#define GA_H   (128 * 64)
#define GB_H   (128 * 64)
#define GST_H  (GA_H + GB_H)      // 16384 halfs = 32KB per stage
#define GSTAGES 3
__global__ __launch_bounds__(256, 2) void gemm_h(
    const __half* __restrict__ A, const __half* __restrict__ Bt,
    const float* __restrict__ bias, float* __restrict__ C,
    int M, int N, int K, int mode)
{
    extern __shared__ __align__(16) __half hsm[];
    const uint32_t sb = smem_u32(hsm);

    const int tid  = threadIdx.x;
    const int wid  = tid >> 5;
    const int lane = tid & 31;
    const int g    = lane >> 2;
    const int t    = lane & 3;
    const int wm   = wid & 3;
    const int wn   = wid >> 2;
    const int m0 = blockIdx.y * 128;
    const int n0 = blockIdx.x * 128;

    const int lrA = tid >> 3;        // 0..31 row base (step 32)
    const int lsA = tid & 7;         // 16B segment

    float c[2][8][4];
#pragma unroll
    for (int mt = 0; mt < 2; ++mt)
#pragma unroll
        for (int nt = 0; nt < 8; ++nt)
#pragma unroll
            for (int j = 0; j < 4; ++j) c[mt][nt][j] = 0.f;

    auto issue = [&](int s) {
        const int base = (s % GSTAGES) * GST_H;
        const int koff = (s << 6) + lsA * 8;
#pragma unroll
        for (int i = 0; i < 4; ++i) {
            int r = lrA + i * 32;
            uint32_t dst = sb + (uint32_t)(base + r * 64 + ((lsA ^ (r & 7)) * 8)) * 2;
            CP_ASYNC16(dst, A + (size_t)(m0 + r) * K + koff);
        }
#pragma unroll
        for (int i = 0; i < 4; ++i) {
            int r = lrA + i * 32;
            uint32_t dst = sb + (uint32_t)(base + GA_H + r * 64 + ((lsA ^ (r & 7)) * 8)) * 2;
            CP_ASYNC16(dst, Bt + (size_t)(n0 + r) * K + koff);
        }
        CP_COMMIT();
    };

    const int KS = K >> 6;
    issue(0);
    issue(1);

#pragma unroll 1
    for (int s = 0; s < KS; ++s) {
        if (s + 1 < KS) { CP_WAIT(1); } else { CP_WAIT(0); }
        __syncthreads();
        if (s + 2 < KS) issue(s + 2);

        const __half* As = hsm + (s % GSTAGES) * GST_H;
        const __half* Bs = As + GA_H;

#pragma unroll
        for (int kt = 0; kt < 4; ++kt) {
            uint32_t bf[8][2];
#pragma unroll
            for (int nt = 0; nt < 8; ++nt) {
                int n = wn * 64 + nt * 8 + g;
                bf[nt][0] = *(const uint32_t*)&Bs[n * 64 + (((2 * kt) ^ g) * 8) + 2 * t];
                bf[nt][1] = *(const uint32_t*)&Bs[n * 64 + (((2 * kt + 1) ^ g) * 8) + 2 * t];
            }
#pragma unroll
            for (int mt = 0; mt < 2; ++mt) {
                int mb = wm * 32 + mt * 16;
                uint32_t a0 = *(const uint32_t*)&As[(mb + g) * 64 + (((2 * kt) ^ g) * 8) + 2 * t];
                uint32_t a1 = *(const uint32_t*)&As[(mb + g + 8) * 64 + (((2 * kt) ^ g) * 8) + 2 * t];
                uint32_t a2 = *(const uint32_t*)&As[(mb + g) * 64 + (((2 * kt + 1) ^ g) * 8) + 2 * t];
                uint32_t a3 = *(const uint32_t*)&As[(mb + g + 8) * 64 + (((2 * kt + 1) ^ g) * 8) + 2 * t];
#pragma unroll
                for (int nt = 0; nt < 8; ++nt)
                    mma_f16(c[mt][nt][0], c[mt][nt][1], c[mt][nt][2], c[mt][nt][3],
                            a0, a1, a2, a3, bf[nt][0], bf[nt][1]);
            }
        }
    }

    // Epilogue: warp covers 64 n-cols -> single which/head region in mode 0.
    const int nbase = n0 + wn * 64;
    if (mode == 0) {
        const int which = nbase >> 10;
        const int h = (nbase & 1023) >> 6;
#pragma unroll
        for (int mt = 0; mt < 2; ++mt) {
            int r0 = m0 + wm * 32 + mt * 16 + g;
            int bb0 = r0 >> 11, tt0 = r0 & (TSEQ - 1);
            int r1 = r0 + 8;
            int bb1 = r1 >> 11, tt1 = r1 & (TSEQ - 1);
            if (which == 2) {
                __half* base0 = g_vh + ((size_t)(bb0 * NHEAD + h)) * HSIZE * TSEQ;
                __half* base1 = g_vh + ((size_t)(bb1 * NHEAD + h)) * HSIZE * TSEQ;
#pragma unroll
                for (int nt = 0; nt < 8; ++nt) {
                    int d = nt * 8 + 2 * t;
                    base0[(size_t)d * TSEQ + tt0]       = __float2half_rn(c[mt][nt][0]);
                    base0[(size_t)(d + 1) * TSEQ + tt0] = __float2half_rn(c[mt][nt][1]);
                    base1[(size_t)d * TSEQ + tt1]       = __float2half_rn(c[mt][nt][2]);
                    base1[(size_t)(d + 1) * TSEQ + tt1] = __float2half_rn(c[mt][nt][3]);
                }
            } else {
                const float sc = (which == 0) ? 0.125f : 1.0f;
                __half* base = (which == 0) ? g_qh : g_kh;
                __half* d0 = base + (((size_t)(bb0 * NHEAD + h) * TSEQ) + tt0) * HSIZE;
                __half* d1 = base + (((size_t)(bb1 * NHEAD + h) * TSEQ) + tt1) * HSIZE;
#pragma unroll
                for (int nt = 0; nt < 8; ++nt) {
                    int d = nt * 8 + 2 * t;
                    *(__half2*)(d0 + d) = __floats2half2_rn(c[mt][nt][0] * sc, c[mt][nt][1] * sc);
                    *(__half2*)(d1 + d) = __floats2half2_rn(c[mt][nt][2] * sc, c[mt][nt][3] * sc);
                }
            }
        }
    } else {
#pragma unroll
        for (int mt = 0; mt < 2; ++mt) {
            int r0 = m0 + wm * 32 + mt * 16 + g;
#pragma unroll
            for (int nt = 0; nt < 8; ++nt) {
                int n = nbase + nt * 8 + 2 * t;
                float2 bv = *(const float2*)(bias + n);
                float2 v0 = {c[mt][nt][0] + bv.x, c[mt][nt][1] + bv.y};
                float2 v1 = {c[mt][nt][2] + bv.x, c[mt][nt][3] + bv.y};
                *(float2*)(C + (size_t)r0 * N + n) = v0;
                *(float2*)(C + (size_t)(r0 + 8) * N + n) = v1;
            }
        }
    }
}

// ---------------------------------------------------------------------------
// fp16 causal flash attention (unchanged from round 10 — known good).
// cp.async double-buffered KV, 128-key tiles. Dyn smem = 98304 B.
// ---------------------------------------------------------------------------
#define AQP_H (128 * 128)
#define AK_H  (128 * 64)
#define KV_H  (AK_H + 64 * 128)   // 16384 halfs per buffer
__global__ __launch_bounds__(256) void attn_h()
{
    extern __shared__ __align__(16) __half asm_[];
    __half* Qs = asm_;
    __half* Ps = Qs;
    const uint32_t sb = smem_u32(asm_);

    const int tid  = threadIdx.x;
    const int wid  = tid >> 5;
    const int lane = tid & 31;
    const int g    = lane >> 2;
    const int t    = lane & 3;
    const int mb   = wid * 16;
    const int bh   = blockIdx.y;
    const int qb   = gridDim.x - 1 - blockIdx.x;   // heavy CTAs first
    const int q0   = qb * 128;

    const __half* Kg = g_kh + (size_t)bh * TSEQ * HSIZE;
    const __half* Vg = g_vh + (size_t)bh * HSIZE * TSEQ;

    auto issueKV = [&](int jt) {
        const int base = AQP_H + (jt & 1) * KV_H;
#pragma unroll
        for (int i = 0; i < 4; ++i) {
            int f = tid + i * 256;
            int kr = f >> 3, ks = f & 7;
            uint32_t dst = sb + (uint32_t)(base + kr * 64 + ((ks ^ (kr & 7)) * 8)) * 2;
            CP_ASYNC16(dst, Kg + (size_t)(jt * 128 + kr) * HSIZE + ks * 8);
        }
#pragma unroll
        for (int i = 0; i < 4; ++i) {
            int f = tid + i * 256;
            int vr = f >> 4, vs = f & 15;
            uint32_t dst = sb + (uint32_t)(base + AK_H + vr * 128 + ((vs ^ (vr & 7)) * 8)) * 2;
            CP_ASYNC16(dst, Vg + (size_t)vr * TSEQ + jt * 128 + vs * 8);
        }
        CP_COMMIT();
    };

    issueKV(0);

    const __half* Qg = g_qh + ((size_t)bh * TSEQ + q0) * HSIZE;
#pragma unroll
    for (int i = 0; i < 4; ++i) {
        int f = tid + i * 256;
        int r = f >> 3, s = f & 7;
        *(uint4*)&Qs[r * 64 + ((s ^ (r & 7)) * 8)] =
            *(const uint4*)(Qg + (size_t)r * HSIZE + s * 8);
    }
    __syncthreads();

    uint32_t qa[4][4];
#pragma unroll
    for (int kb = 0; kb < 4; ++kb) {
        qa[kb][0] = *(const uint32_t*)&Qs[(mb + g) * 64 + (((2 * kb) ^ g) * 8) + 2 * t];
        qa[kb][1] = *(const uint32_t*)&Qs[(mb + g + 8) * 64 + (((2 * kb) ^ g) * 8) + 2 * t];
        qa[kb][2] = *(const uint32_t*)&Qs[(mb + g) * 64 + (((2 * kb + 1) ^ g) * 8) + 2 * t];
        qa[kb][3] = *(const uint32_t*)&Qs[(mb + g + 8) * 64 + (((2 * kb + 1) ^ g) * 8) + 2 * t];
    }

    float o[8][4];
#pragma unroll
    for (int nt = 0; nt < 8; ++nt)
#pragma unroll
        for (int j = 0; j < 4; ++j) o[nt][j] = 0.f;
    float m0 = -INFINITY, m1 = -INFINITY, l0 = 0.f, l1 = 0.f;

    const int row0 = q0 + mb + g;
    const int row1 = row0 + 8;

    for (int jt = 0; jt <= qb; ++jt) {
        CP_WAIT(0);
        __syncthreads();
        if (jt < qb) issueKV(jt + 1);

        const __half* Ks = asm_ + AQP_H + (jt & 1) * KV_H;
        const __half* Vs = Ks + AK_H;

        float s[16][4];
#pragma unroll
        for (int nt = 0; nt < 16; ++nt)
#pragma unroll
            for (int j = 0; j < 4; ++j) s[nt][j] = 0.f;
#pragma unroll
        for (int kb = 0; kb < 4; ++kb) {
#pragma unroll
            for (int nt = 0; nt < 16; ++nt) {
                int n = nt * 8 + g;
                uint32_t b0 = *(const uint32_t*)&Ks[n * 64 + (((2 * kb) ^ g) * 8) + 2 * t];
                uint32_t b1 = *(const uint32_t*)&Ks[n * 64 + (((2 * kb + 1) ^ g) * 8) + 2 * t];
                mma_f16(s[nt][0], s[nt][1], s[nt][2], s[nt][3],
                        qa[kb][0], qa[kb][1], qa[kb][2], qa[kb][3], b0, b1);
            }
        }

        if (jt == qb) {
#pragma unroll
            for (int nt = 0; nt < 16; ++nt) {
                int col = jt * 128 + nt * 8 + 2 * t;
                if (col > row0)     s[nt][0] = -INFINITY;
                if (col + 1 > row0) s[nt][1] = -INFINITY;
                if (col > row1)     s[nt][2] = -INFINITY;
                if (col + 1 > row1) s[nt][3] = -INFINITY;
            }
        }

        float mx0 = -INFINITY, mx1 = -INFINITY;
#pragma unroll
        for (int nt = 0; nt < 16; ++nt) {
            mx0 = fmaxf(mx0, fmaxf(s[nt][0], s[nt][1]));
            mx1 = fmaxf(mx1, fmaxf(s[nt][2], s[nt][3]));
        }
        mx0 = fmaxf(mx0, __shfl_xor_sync(0xffffffffu, mx0, 1));
        mx0 = fmaxf(mx0, __shfl_xor_sync(0xffffffffu, mx0, 2));
        mx1 = fmaxf(mx1, __shfl_xor_sync(0xffffffffu, mx1, 1));
        mx1 = fmaxf(mx1, __shfl_xor_sync(0xffffffffu, mx1, 2));
        float nm0 = fmaxf(m0, mx0), nm1 = fmaxf(m1, mx1);
        float cr0 = __expf(m0 - nm0), cr1 = __expf(m1 - nm1);
        l0 *= cr0; l1 *= cr1;
#pragma unroll
        for (int nt = 0; nt < 8; ++nt) {
            o[nt][0] *= cr0; o[nt][1] *= cr0;
            o[nt][2] *= cr1; o[nt][3] *= cr1;
        }
        float s0 = 0.f, s1 = 0.f;
#pragma unroll
        for (int nt = 0; nt < 16; ++nt) {
            float p00 = __expf(s[nt][0] - nm0);
            float p01 = __expf(s[nt][1] - nm0);
            float p10 = __expf(s[nt][2] - nm1);
            float p11 = __expf(s[nt][3] - nm1);
            s0 += p00 + p01; s1 += p10 + p11;
            *(__half2*)&Ps[(mb + g) * 128 + ((nt ^ g) * 8) + 2 * t] =
                __floats2half2_rn(p00, p01);
            *(__half2*)&Ps[(mb + g + 8) * 128 + ((nt ^ g) * 8) + 2 * t] =
                __floats2half2_rn(p10, p11);
        }
        s0 += __shfl_xor_sync(0xffffffffu, s0, 1);
        s0 += __shfl_xor_sync(0xffffffffu, s0, 2);
        s1 += __shfl_xor_sync(0xffffffffu, s1, 1);
        s1 += __shfl_xor_sync(0xffffffffu, s1, 2);
        l0 += s0; l1 += s1;
        m0 = nm0; m1 = nm1;
        __syncwarp();

#pragma unroll
        for (int kb = 0; kb < 8; ++kb) {
            uint32_t pa0 = *(const uint32_t*)&Ps[(mb + g) * 128 + (((2 * kb) ^ g) * 8) + 2 * t];
            uint32_t pa1 = *(const uint32_t*)&Ps[(mb + g + 8) * 128 + (((2 * kb) ^ g) * 8) + 2 * t];
            uint32_t pa2 = *(const uint32_t*)&Ps[(mb + g) * 128 + (((2 * kb + 1) ^ g) * 8) + 2 * t];
            uint32_t pa3 = *(const uint32_t*)&Ps[(mb + g + 8) * 128 + (((2 * kb + 1) ^ g) * 8) + 2 * t];
#pragma unroll
            for (int nt = 0; nt < 8; ++nt) {
                int n = nt * 8 + g;
                uint32_t b0 = *(const uint32_t*)&Vs[n * 128 + (((2 * kb) ^ g) * 8) + 2 * t];
                uint32_t b1 = *(const uint32_t*)&Vs[n * 128 + (((2 * kb + 1) ^ g) * 8) + 2 * t];
                mma_f16(o[nt][0], o[nt][1], o[nt][2], o[nt][3],
                        pa0, pa1, pa2, pa3, b0, b1);
            }
        }
    }

    const int b = bh >> 4, h = bh & 15;
    const float inv0 = 1.f / l0, inv1 = 1.f / l1;
    __half* O0 = g_ah + ((size_t)(b * TSEQ) + row0) * CEMB + h * HSIZE;
    __half* O1 = g_ah + ((size_t)(b * TSEQ) + row1) * CEMB + h * HSIZE;
#pragma unroll
    for (int nt = 0; nt < 8; ++nt) {
        int d = nt * 8 + 2 * t;
        *(__half2*)(O0 + d) = __floats2half2_rn(o[nt][0] * inv0, o[nt][1] * inv0);
        *(__half2*)(O1 + d) = __floats2half2_rn(o[nt][2] * inv1, o[nt][3] * inv1);
    }
}

// ---------------------------------------------------------------------------
extern "C" void kernel_launch(void* const* d_in, const int* in_sizes, int n_in,
                              void* d_out, int out_size)
{
    const float* x      = (const float*)d_in[0];
    const float* w_qkv  = (const float*)d_in[1];
    const float* w_proj = (const float*)d_in[2];
    const float* b_proj = (const float*)d_in[3];
    float* out = (float*)d_out;

    __half *xh = nullptr, *ah = nullptr, *wtq = nullptr, *wtp = nullptr;
    cudaGetSymbolAddress((void**)&xh,  g_xh);
    cudaGetSymbolAddress((void**)&ah,  g_ah);
    cudaGetSymbolAddress((void**)&wtq, g_wtq);
    cudaGetSymbolAddress((void**)&wtp, g_wtp);

    const int ATTN_SMEM = (AQP_H + 2 * KV_H) * 2;       // 98304
    const int GEMM_SMEM = GSTAGES * GST_H * 2;          // 98304
    cudaFuncSetAttribute(attn_h, cudaFuncAttributeMaxDynamicSharedMemorySize, ATTN_SMEM);
    cudaFuncSetAttribute(gemm_h, cudaFuncAttributeMaxDynamicSharedMemorySize, GEMM_SMEM);

    // 0) convert x, transpose weights (K-major, half)
    cvt_x<<<MROWS * CEMB / (256 * 8), 256>>>(x, xh);
    transpose_h<<<dim3(3 * CEMB / 32, CEMB / 32), dim3(32, 8)>>>(w_qkv, wtq, CEMB, 3 * CEMB);
    transpose_h<<<dim3(CEMB / 32, CEMB / 32), dim3(32, 8)>>>(w_proj, wtp, CEMB, CEMB);

    // 1) QKV GEMM (fp16 mma, cp.async, 2 CTA/SM) + head-major scatter
    gemm_h<<<dim3(3 * CEMB / 128, MROWS / 128), 256, GEMM_SMEM>>>(
        xh, wtq, nullptr, nullptr, MROWS, 3 * CEMB, CEMB, 0);

    // 2) Causal flash attention (fp16 mma, cp.async double-buffered KV)
    attn_h<<<dim3(TSEQ / 128, BATCH * NHEAD), 256, ATTN_SMEM>>>();

    // 3) Output projection + bias (fp16 mma, fp32 out)
    gemm_h<<<dim3(CEMB / 128, MROWS / 128), 256, GEMM_SMEM>>>(
        ah, wtp, b_proj, out, MROWS, CEMB, CEMB, 1);
}